// round 6
// baseline (speedup 1.0000x reference)
#include <cuda_runtime.h>
#include <cuda_bf16.h>
#include <math.h>
#include <stdint.h>

// Problem dims
#define Bz   2
#define Sq   2048
#define Dm   1024
#define Hn   16
#define DH   64
#define DFF  4096
#define Mrows (Bz * Sq)      // 4096
#define BH   (Bz * Hn)       // 32

// ---------------- scratch ----------------------------------------------------
__device__ float g_xn[(size_t)Mrows * Dm];
__device__ float g_qkv[(size_t)Mrows * 3 * Dm];
__device__ float g_attnout[(size_t)Mrows * Dm];
__device__ float g_x2[(size_t)Mrows * Dm];
__device__ float g_h[(size_t)Mrows * DFF];

// ---------------- helpers ----------------------------------------------------
__device__ __forceinline__ uint32_t f2tf32(float f) {
    uint32_t u;
    asm("cvt.rna.tf32.f32 %0, %1;" : "=r"(u) : "f"(f));
    return u;
}

__device__ __forceinline__ void mma_tf32(float c[4],
    uint32_t a0, uint32_t a1, uint32_t a2, uint32_t a3,
    uint32_t b0, uint32_t b1)
{
    asm volatile(
        "mma.sync.aligned.m16n8k8.row.col.f32.tf32.tf32.f32 "
        "{%0,%1,%2,%3}, {%4,%5,%6,%7}, {%8,%9}, {%0,%1,%2,%3};\n"
        : "+f"(c[0]), "+f"(c[1]), "+f"(c[2]), "+f"(c[3])
        : "r"(a0), "r"(a1), "r"(a2), "r"(a3), "r"(b0), "r"(b1));
}

// k-permutation within each 8-group: puts k and k+4 adjacent
__device__ __forceinline__ int permk(int k) {
    return (k & 24) | ((k & 3) << 1) | ((k >> 2) & 1);
}

// ---------------- RMSNorm ----------------------------------------------------
__global__ __launch_bounds__(256)
void rmsnorm_kernel(const float* __restrict__ x, const float* __restrict__ scale,
                    float* __restrict__ out)
{
    int row = blockIdx.x;
    const float* xr = x + (size_t)row * Dm;
    float ss = 0.f;
    #pragma unroll
    for (int i = threadIdx.x; i < Dm; i += 256) { float v = xr[i]; ss += v * v; }
    __shared__ float red[256];
    red[threadIdx.x] = ss; __syncthreads();
    #pragma unroll
    for (int s = 128; s > 0; s >>= 1) {
        if (threadIdx.x < s) red[threadIdx.x] += red[threadIdx.x + s];
        __syncthreads();
    }
    float rms = rsqrtf(red[0] * (1.0f / Dm) + 1e-8f);
    float* orow = out + (size_t)row * Dm;
    #pragma unroll
    for (int i = threadIdx.x; i < Dm; i += 256)
        orow[i] = scale[i] * xr[i] * rms;
}

// ---------------- TF32 tensor-core GEMM, vectorized fragment loads -----------
// C = A[M,K] @ B[K,N].  EPI: 0 = +bias, 1 = +bias+residual, 2 = +bias, gelu
// Block tile 128x128, warp tile 64x32 (8 warps), K-chunk 32.
// A smem: [m][permk(k)]  stride 40  -> fragment loads are LDS.64, conflict-free
// B smem: [k][(n&7)*16 + (n>>3)] stride 132 -> fragment loads are LDS.128, conflict-free
#define AS_STRIDE 40
#define BS_STRIDE 132

template<int EPI>
__global__ __launch_bounds__(256, 2)
void gemm_tc(const float* __restrict__ A, const float* __restrict__ Bm,
             const float* __restrict__ bias, const float* __restrict__ resid,
             float* __restrict__ C, int M, int N, int K)
{
    __shared__ __align__(16) uint32_t As[128 * AS_STRIDE];
    __shared__ __align__(16) uint32_t Bs[32 * BS_STRIDE];

    const int tid = threadIdx.x, warp = tid >> 5, lane = tid & 31;
    const int bm = blockIdx.y * 128, bn = blockIdx.x * 128;
    const int warpM = (warp & 1) * 64, warpN = (warp >> 1) * 32;
    const int r0 = lane >> 2, c0 = lane & 3;
    const int wq = warpN >> 3;            // 0,4,8,12
    float c[4][4][4] = {};

    // loader coords
    const int am  = tid >> 1;             // A row 0..127
    const int acb = (tid & 1) * 16;       // A col base
    const int bk  = tid >> 3;             // B row 0..31
    const int bnb = (tid & 7) * 16;       // B col base

    for (int k0 = 0; k0 < K; k0 += 32) {
        __syncthreads();
        // ---- A tile: 128 x 32, store k-permuted ----
        {
            const float* ga = &A[(size_t)(bm + am) * K + k0 + acb];
            uint32_t* dst = &As[am * AS_STRIDE];
            #pragma unroll
            for (int j = 0; j < 4; j++) {
                float4 v = *(const float4*)(ga + j * 4);
                int kb = acb + j * 4;
                dst[permk(kb + 0)] = f2tf32(v.x);
                dst[permk(kb + 1)] = f2tf32(v.y);
                dst[permk(kb + 2)] = f2tf32(v.z);
                dst[permk(kb + 3)] = f2tf32(v.w);
            }
        }
        // ---- B tile: 32 x 128, store n-permuted ----
        {
            const float* gb = &Bm[(size_t)(k0 + bk) * N + bn + bnb];
            uint32_t* dst = &Bs[bk * BS_STRIDE];
            #pragma unroll
            for (int j = 0; j < 4; j++) {
                float4 v = *(const float4*)(gb + j * 4);
                int n0 = bnb + j * 4;
                dst[((n0 + 0) & 7) * 16 + ((n0 + 0) >> 3)] = f2tf32(v.x);
                dst[((n0 + 1) & 7) * 16 + ((n0 + 1) >> 3)] = f2tf32(v.y);
                dst[((n0 + 2) & 7) * 16 + ((n0 + 2) >> 3)] = f2tf32(v.z);
                dst[((n0 + 3) & 7) * 16 + ((n0 + 3) >> 3)] = f2tf32(v.w);
            }
        }
        __syncthreads();

        #pragma unroll
        for (int kk = 0; kk < 32; kk += 8) {
            uint32_t a[4][4];
            #pragma unroll
            for (int mt = 0; mt < 4; mt++) {
                int m = warpM + mt * 16;
                uint2 f0 = *(const uint2*)&As[(m + r0) * AS_STRIDE + kk + 2 * c0];
                uint2 f1 = *(const uint2*)&As[(m + r0 + 8) * AS_STRIDE + kk + 2 * c0];
                a[mt][0] = f0.x; a[mt][1] = f1.x; a[mt][2] = f0.y; a[mt][3] = f1.y;
            }
            uint4 bv0 = *(const uint4*)&Bs[(kk + c0) * BS_STRIDE + r0 * 16 + wq];
            uint4 bv1 = *(const uint4*)&Bs[(kk + c0 + 4) * BS_STRIDE + r0 * 16 + wq];
            uint32_t bb[4][2] = {{bv0.x, bv1.x}, {bv0.y, bv1.y},
                                 {bv0.z, bv1.z}, {bv0.w, bv1.w}};
            #pragma unroll
            for (int mt = 0; mt < 4; mt++)
                #pragma unroll
                for (int nt = 0; nt < 4; nt++)
                    mma_tf32(c[mt][nt], a[mt][0], a[mt][1], a[mt][2], a[mt][3],
                             bb[nt][0], bb[nt][1]);
        }
    }

    #pragma unroll
    for (int mt = 0; mt < 4; mt++) {
        #pragma unroll
        for (int nt = 0; nt < 4; nt++) {
            #pragma unroll
            for (int ci = 0; ci < 4; ci++) {
                int row = bm + warpM + mt * 16 + r0 + ((ci >= 2) ? 8 : 0);
                int col = bn + warpN + nt * 8 + c0 * 2 + (ci & 1);
                float v = c[mt][nt][ci] + bias[col];
                if (EPI == 1) v += resid[(size_t)row * N + col];
                if (EPI == 2) v = 0.5f * v * (1.0f + erff(v * 0.70710678118654752f));
                C[(size_t)row * N + col] = v;
            }
        }
    }
}

// ---------------- fused flash attention --------------------------------------
#define QS_STRIDE 68
#define KS_STRIDE 68
#define VS_STRIDE 72
#define PS_STRIDE 68
#define FLASH_SMEM ((128 * QS_STRIDE + 64 * KS_STRIDE + 64 * VS_STRIDE + 128 * PS_STRIDE) * 4)

__global__ __launch_bounds__(256, 2)
void flash_attn(const float* __restrict__ qkv, float* __restrict__ attnout)
{
    extern __shared__ uint32_t sm[];
    uint32_t* Qs = sm;
    uint32_t* Ks = Qs + 128 * QS_STRIDE;
    uint32_t* Vs = Ks + 64 * KS_STRIDE;
    uint32_t* Ps = Vs + 64 * VS_STRIDE;

    const int bh = blockIdx.y, b = bh >> 4, h = bh & 15;
    const int q0 = blockIdx.x * 128;
    const int tid = threadIdx.x, warp = tid >> 5, lane = tid & 31;
    const int r0 = lane >> 2, c0 = lane & 3;
    const int qrow = warp * 16;
    const float slope = exp2f(-0.5f * (float)(h + 1));
    const size_t base = (size_t)b * Sq * (3 * Dm) + (size_t)h * DH;

    #pragma unroll
    for (int p = 0; p < 8; p++) {
        int idx = tid + p * 256;
        int r = idx >> 4, d4 = idx & 15;
        float4 v = *(const float4*)&qkv[base + (size_t)(q0 + r) * (3 * Dm) + d4 * 4];
        uint32_t* dst = &Qs[r * QS_STRIDE + d4 * 4];
        dst[0] = f2tf32(v.x); dst[1] = f2tf32(v.y);
        dst[2] = f2tf32(v.z); dst[3] = f2tf32(v.w);
    }

    float m_i[2] = {-1e30f, -1e30f};
    float l_i[2] = {0.f, 0.f};
    float o[8][4] = {};

    for (int t0 = 0; t0 < Sq; t0 += 64) {
        __syncthreads();
        #pragma unroll
        for (int p = 0; p < 4; p++) {
            int idx = tid + p * 256;
            int r = idx >> 4, d4 = idx & 15;
            const float* src = &qkv[base + (size_t)(t0 + r) * (3 * Dm) + d4 * 4];
            float4 vk = *(const float4*)(src + Dm);
            float4 vv = *(const float4*)(src + 2 * Dm);
            uint32_t* dk = &Ks[r * KS_STRIDE + d4 * 4];
            dk[0] = f2tf32(vk.x); dk[1] = f2tf32(vk.y);
            dk[2] = f2tf32(vk.z); dk[3] = f2tf32(vk.w);
            uint32_t* dv = &Vs[r * VS_STRIDE + d4 * 4];
            dv[0] = f2tf32(vv.x); dv[1] = f2tf32(vv.y);
            dv[2] = f2tf32(vv.z); dv[3] = f2tf32(vv.w);
        }
        __syncthreads();

        float s[8][4] = {};
        #pragma unroll
        for (int kk = 0; kk < 64; kk += 8) {
            uint32_t a0 = Qs[(qrow + r0) * QS_STRIDE + kk + c0];
            uint32_t a1 = Qs[(qrow + r0 + 8) * QS_STRIDE + kk + c0];
            uint32_t a2 = Qs[(qrow + r0) * QS_STRIDE + kk + c0 + 4];
            uint32_t a3 = Qs[(qrow + r0 + 8) * QS_STRIDE + kk + c0 + 4];
            #pragma unroll
            for (int nt = 0; nt < 8; nt++) {
                uint32_t b0 = Ks[(nt * 8 + r0) * KS_STRIDE + kk + c0];
                uint32_t b1 = Ks[(nt * 8 + r0) * KS_STRIDE + kk + c0 + 4];
                mma_tf32(s[nt], a0, a1, a2, a3, b0, b1);
            }
        }

        const int si0 = q0 + qrow + r0, si1 = si0 + 8;
        float mx0 = -1e30f, mx1 = -1e30f;
        #pragma unroll
        for (int nt = 0; nt < 8; nt++) {
            int tj = t0 + nt * 8 + c0 * 2;
            s[nt][0] = s[nt][0] * 0.125f - slope * fabsf((float)(si0 - tj));
            s[nt][1] = s[nt][1] * 0.125f - slope * fabsf((float)(si0 - tj - 1));
            s[nt][2] = s[nt][2] * 0.125f - slope * fabsf((float)(si1 - tj));
            s[nt][3] = s[nt][3] * 0.125f - slope * fabsf((float)(si1 - tj - 1));
            mx0 = fmaxf(mx0, fmaxf(s[nt][0], s[nt][1]));
            mx1 = fmaxf(mx1, fmaxf(s[nt][2], s[nt][3]));
        }
        mx0 = fmaxf(mx0, __shfl_xor_sync(0xffffffffu, mx0, 1));
        mx0 = fmaxf(mx0, __shfl_xor_sync(0xffffffffu, mx0, 2));
        mx1 = fmaxf(mx1, __shfl_xor_sync(0xffffffffu, mx1, 1));
        mx1 = fmaxf(mx1, __shfl_xor_sync(0xffffffffu, mx1, 2));

        float mn0 = fmaxf(m_i[0], mx0), mn1 = fmaxf(m_i[1], mx1);
        float corr0 = __expf(m_i[0] - mn0), corr1 = __expf(m_i[1] - mn1);
        m_i[0] = mn0; m_i[1] = mn1;

        float sum0 = 0.f, sum1 = 0.f;
        #pragma unroll
        for (int nt = 0; nt < 8; nt++) {
            s[nt][0] = __expf(s[nt][0] - mn0);
            s[nt][1] = __expf(s[nt][1] - mn0);
            s[nt][2] = __expf(s[nt][2] - mn1);
            s[nt][3] = __expf(s[nt][3] - mn1);
            sum0 += s[nt][0] + s[nt][1];
            sum1 += s[nt][2] + s[nt][3];
            uint32_t* d0 = &Ps[(qrow + r0) * PS_STRIDE + nt * 8 + c0 * 2];
            d0[0] = f2tf32(s[nt][0]); d0[1] = f2tf32(s[nt][1]);
            uint32_t* d1 = &Ps[(qrow + r0 + 8) * PS_STRIDE + nt * 8 + c0 * 2];
            d1[0] = f2tf32(s[nt][2]); d1[1] = f2tf32(s[nt][3]);
        }
        sum0 += __shfl_xor_sync(0xffffffffu, sum0, 1);
        sum0 += __shfl_xor_sync(0xffffffffu, sum0, 2);
        sum1 += __shfl_xor_sync(0xffffffffu, sum1, 1);
        sum1 += __shfl_xor_sync(0xffffffffu, sum1, 2);
        l_i[0] = l_i[0] * corr0 + sum0;
        l_i[1] = l_i[1] * corr1 + sum1;
        #pragma unroll
        for (int nt = 0; nt < 8; nt++) {
            o[nt][0] *= corr0; o[nt][1] *= corr0;
            o[nt][2] *= corr1; o[nt][3] *= corr1;
        }
        __syncwarp();

        #pragma unroll
        for (int kk = 0; kk < 64; kk += 8) {
            uint32_t a0 = Ps[(qrow + r0) * PS_STRIDE + kk + c0];
            uint32_t a1 = Ps[(qrow + r0 + 8) * PS_STRIDE + kk + c0];
            uint32_t a2 = Ps[(qrow + r0) * PS_STRIDE + kk + c0 + 4];
            uint32_t a3 = Ps[(qrow + r0 + 8) * PS_STRIDE + kk + c0 + 4];
            #pragma unroll
            for (int nt = 0; nt < 8; nt++) {
                uint32_t b0 = Vs[(kk + c0) * VS_STRIDE + nt * 8 + r0];
                uint32_t b1 = Vs[(kk + c0 + 4) * VS_STRIDE + nt * 8 + r0];
                mma_tf32(o[nt], a0, a1, a2, a3, b0, b1);
            }
        }
    }

    float inv0 = 1.f / l_i[0], inv1 = 1.f / l_i[1];
    size_t obase = ((size_t)b * Sq + q0 + qrow) * Dm + (size_t)h * DH;
    #pragma unroll
    for (int nt = 0; nt < 8; nt++) {
        int d = nt * 8 + c0 * 2;
        attnout[obase + (size_t)r0 * Dm + d]           = o[nt][0] * inv0;
        attnout[obase + (size_t)r0 * Dm + d + 1]       = o[nt][1] * inv0;
        attnout[obase + (size_t)(r0 + 8) * Dm + d]     = o[nt][2] * inv1;
        attnout[obase + (size_t)(r0 + 8) * Dm + d + 1] = o[nt][3] * inv1;
    }
}

// ---------------- host driver ------------------------------------------------
extern "C" void kernel_launch(void* const* d_in, const int* in_sizes, int n_in,
                              void* d_out, int out_size)
{
    const float* x      = (const float*)d_in[0];
    const float* scale1 = (const float*)d_in[1];
    const float* scale2 = (const float*)d_in[2];
    const float* w_qkv  = (const float*)d_in[3];
    const float* b_qkv  = (const float*)d_in[4];
    const float* w_out  = (const float*)d_in[5];
    const float* b_out  = (const float*)d_in[6];
    const float* w1     = (const float*)d_in[7];
    const float* b1     = (const float*)d_in[8];
    const float* w2     = (const float*)d_in[9];
    const float* b2     = (const float*)d_in[10];
    float* out = (float*)d_out;

    void *p_xn, *p_qkv, *p_attnout, *p_x2, *p_h;
    cudaGetSymbolAddress(&p_xn, g_xn);
    cudaGetSymbolAddress(&p_qkv, g_qkv);
    cudaGetSymbolAddress(&p_attnout, g_attnout);
    cudaGetSymbolAddress(&p_x2, g_x2);
    cudaGetSymbolAddress(&p_h, g_h);
    float* xn      = (float*)p_xn;
    float* qkv     = (float*)p_qkv;
    float* attnout = (float*)p_attnout;
    float* x2      = (float*)p_x2;
    float* hbuf    = (float*)p_h;

    cudaFuncSetAttribute(flash_attn, cudaFuncAttributeMaxDynamicSharedMemorySize,
                         FLASH_SMEM);

    // 1) RMSNorm 1
    rmsnorm_kernel<<<Mrows, 256>>>(x, scale1, xn);

    // 2) QKV projection
    gemm_tc<0><<<dim3(3 * Dm / 128, Mrows / 128), 256>>>(
        xn, w_qkv, b_qkv, nullptr, qkv, Mrows, 3 * Dm, Dm);

    // 3-5) fused attention
    flash_attn<<<dim3(Sq / 128, BH), 256, FLASH_SMEM>>>(qkv, attnout);

    // 6) out projection + residual
    gemm_tc<1><<<dim3(Dm / 128, Mrows / 128), 256>>>(
        attnout, w_out, b_out, x, x2, Mrows, Dm, Dm);

    // 7) RMSNorm 2
    rmsnorm_kernel<<<Mrows, 256>>>(x2, scale2, xn);

    // 8) FFN up + GELU
    gemm_tc<2><<<dim3(DFF / 128, Mrows / 128), 256>>>(
        xn, w1, b1, nullptr, hbuf, Mrows, DFF, Dm);

    // 9) FFN down + residual
    gemm_tc<1><<<dim3(Dm / 128, Mrows / 128), 256>>>(
        hbuf, w2, b2, x2, out, Mrows, Dm, DFF);
}

// round 7
// speedup vs baseline: 1.6613x; 1.6613x over previous
#include <cuda_runtime.h>
#include <cuda_bf16.h>
#include <math.h>
#include <stdint.h>

// Problem dims
#define Bz   2
#define Sq   2048
#define Dm   1024
#define Hn   16
#define DH   64
#define DFF  4096
#define Mrows (Bz * Sq)      // 4096
#define BH   (Bz * Hn)       // 32

// ---------------- scratch ----------------------------------------------------
__device__ float g_xn[(size_t)Mrows * Dm];
__device__ float g_qkv[(size_t)Mrows * 3 * Dm];
__device__ float g_attnout[(size_t)Mrows * Dm];
__device__ float g_x2[(size_t)Mrows * Dm];
__device__ float g_h[(size_t)Mrows * DFF];

// ---------------- helpers ----------------------------------------------------
__device__ __forceinline__ uint32_t f2tf32(float f) {
    uint32_t u;
    asm("cvt.rna.tf32.f32 %0, %1;" : "=r"(u) : "f"(f));
    return u;
}

__device__ __forceinline__ void mma_tf32(float c[4],
    uint32_t a0, uint32_t a1, uint32_t a2, uint32_t a3,
    uint32_t b0, uint32_t b1)
{
    asm volatile(
        "mma.sync.aligned.m16n8k8.row.col.f32.tf32.tf32.f32 "
        "{%0,%1,%2,%3}, {%4,%5,%6,%7}, {%8,%9}, {%0,%1,%2,%3};\n"
        : "+f"(c[0]), "+f"(c[1]), "+f"(c[2]), "+f"(c[3])
        : "r"(a0), "r"(a1), "r"(a2), "r"(a3), "r"(b0), "r"(b1));
}

// ---------------- RMSNorm ----------------------------------------------------
__global__ __launch_bounds__(256)
void rmsnorm_kernel(const float* __restrict__ x, const float* __restrict__ scale,
                    float* __restrict__ out)
{
    int row = blockIdx.x;
    const float* xr = x + (size_t)row * Dm;
    float ss = 0.f;
    #pragma unroll
    for (int i = threadIdx.x; i < Dm; i += 256) { float v = xr[i]; ss += v * v; }
    __shared__ float red[256];
    red[threadIdx.x] = ss; __syncthreads();
    #pragma unroll
    for (int s = 128; s > 0; s >>= 1) {
        if (threadIdx.x < s) red[threadIdx.x] += red[threadIdx.x + s];
        __syncthreads();
    }
    float rms = rsqrtf(red[0] * (1.0f / Dm) + 1e-8f);
    float* orow = out + (size_t)row * Dm;
    #pragma unroll
    for (int i = threadIdx.x; i < Dm; i += 256)
        orow[i] = scale[i] * xr[i] * rms;
}

// ---------------- TF32 tensor-core GEMM: C = A[M,K] @ B[K,N] -----------------
// EPI: 0 = +bias, 1 = +bias+residual, 2 = +bias then exact gelu
// Block tile 128x128, 4 warps, warp tile 64x64 (mt=4, nt=8), K-chunk 32.
// Geometry chosen to minimize smem crossbar bytes per mma (A rep x2, B rep x2).
#define AS_STRIDE 36
#define BS_STRIDE 136

template<int EPI>
__global__ __launch_bounds__(128, 2)
void gemm_tc(const float* __restrict__ A, const float* __restrict__ Bm,
             const float* __restrict__ bias, const float* __restrict__ resid,
             float* __restrict__ C, int M, int N, int K)
{
    __shared__ uint32_t As[128 * AS_STRIDE];   // [m][k]
    __shared__ uint32_t Bs[32 * BS_STRIDE];    // [k][n]
    const int tid = threadIdx.x, warp = tid >> 5, lane = tid & 31;
    const int bm = blockIdx.y * 128, bn = blockIdx.x * 128;
    const int warpM = (warp & 1) * 64, warpN = (warp >> 1) * 64;
    const int r0 = lane >> 2, c0 = lane & 3;
    float c[4][8][4] = {};

    for (int k0 = 0; k0 < K; k0 += 32) {
        __syncthreads();
        // A tile: 128 rows x 32 k = 1024 float4 / 128 thr = 8 each
        #pragma unroll
        for (int p = 0; p < 8; p++) {
            int idx = tid + p * 128;
            int m = idx >> 3, k4 = idx & 7;
            float4 v = *(const float4*)&A[(size_t)(bm + m) * K + k0 + k4 * 4];
            uint32_t* dst = &As[m * AS_STRIDE + k4 * 4];
            dst[0] = f2tf32(v.x); dst[1] = f2tf32(v.y);
            dst[2] = f2tf32(v.z); dst[3] = f2tf32(v.w);
        }
        // B tile: 32 k x 128 n = 1024 float4 / 128 thr = 8 each
        #pragma unroll
        for (int p = 0; p < 8; p++) {
            int idx = tid + p * 128;
            int k = idx >> 5, n4 = idx & 31;
            float4 v = *(const float4*)&Bm[(size_t)(k0 + k) * N + bn + n4 * 4];
            uint32_t* dst = &Bs[k * BS_STRIDE + n4 * 4];
            dst[0] = f2tf32(v.x); dst[1] = f2tf32(v.y);
            dst[2] = f2tf32(v.z); dst[3] = f2tf32(v.w);
        }
        __syncthreads();

        #pragma unroll
        for (int kk = 0; kk < 32; kk += 8) {
            uint32_t a[4][4], b[8][2];
            #pragma unroll
            for (int mt = 0; mt < 4; mt++) {
                int m = warpM + mt * 16;
                a[mt][0] = As[(m + r0) * AS_STRIDE + kk + c0];
                a[mt][1] = As[(m + r0 + 8) * AS_STRIDE + kk + c0];
                a[mt][2] = As[(m + r0) * AS_STRIDE + kk + c0 + 4];
                a[mt][3] = As[(m + r0 + 8) * AS_STRIDE + kk + c0 + 4];
            }
            #pragma unroll
            for (int nt = 0; nt < 8; nt++) {
                int n = warpN + nt * 8 + r0;
                b[nt][0] = Bs[(kk + c0) * BS_STRIDE + n];
                b[nt][1] = Bs[(kk + c0 + 4) * BS_STRIDE + n];
            }
            #pragma unroll
            for (int mt = 0; mt < 4; mt++)
                #pragma unroll
                for (int nt = 0; nt < 8; nt++)
                    mma_tf32(c[mt][nt], a[mt][0], a[mt][1], a[mt][2], a[mt][3],
                             b[nt][0], b[nt][1]);
        }
    }

    #pragma unroll
    for (int mt = 0; mt < 4; mt++) {
        #pragma unroll
        for (int nt = 0; nt < 8; nt++) {
            #pragma unroll
            for (int ci = 0; ci < 4; ci++) {
                int row = bm + warpM + mt * 16 + r0 + ((ci >= 2) ? 8 : 0);
                int col = bn + warpN + nt * 8 + c0 * 2 + (ci & 1);
                float v = c[mt][nt][ci] + bias[col];
                if (EPI == 1) v += resid[(size_t)row * N + col];
                if (EPI == 2) v = 0.5f * v * (1.0f + erff(v * 0.70710678118654752f));
                C[(size_t)row * N + col] = v;
            }
        }
    }
}

// ---------------- fused flash attention --------------------------------------
#define QS_STRIDE 68
#define KS_STRIDE 68
#define VS_STRIDE 72
#define PS_STRIDE 68
#define FLASH_SMEM ((128 * QS_STRIDE + 64 * KS_STRIDE + 64 * VS_STRIDE + 128 * PS_STRIDE) * 4)

__global__ __launch_bounds__(256, 2)
void flash_attn(const float* __restrict__ qkv, float* __restrict__ attnout)
{
    extern __shared__ uint32_t sm[];
    uint32_t* Qs = sm;
    uint32_t* Ks = Qs + 128 * QS_STRIDE;
    uint32_t* Vs = Ks + 64 * KS_STRIDE;
    uint32_t* Ps = Vs + 64 * VS_STRIDE;

    const int bh = blockIdx.y, b = bh >> 4, h = bh & 15;
    const int q0 = blockIdx.x * 128;
    const int tid = threadIdx.x, warp = tid >> 5, lane = tid & 31;
    const int r0 = lane >> 2, c0 = lane & 3;
    const int qrow = warp * 16;
    const float slope = exp2f(-0.5f * (float)(h + 1));
    const size_t base = (size_t)b * Sq * (3 * Dm) + (size_t)h * DH;

    #pragma unroll
    for (int p = 0; p < 8; p++) {
        int idx = tid + p * 256;
        int r = idx >> 4, d4 = idx & 15;
        float4 v = *(const float4*)&qkv[base + (size_t)(q0 + r) * (3 * Dm) + d4 * 4];
        uint32_t* dst = &Qs[r * QS_STRIDE + d4 * 4];
        dst[0] = f2tf32(v.x); dst[1] = f2tf32(v.y);
        dst[2] = f2tf32(v.z); dst[3] = f2tf32(v.w);
    }

    float m_i[2] = {-1e30f, -1e30f};
    float l_i[2] = {0.f, 0.f};
    float o[8][4] = {};

    for (int t0 = 0; t0 < Sq; t0 += 64) {
        __syncthreads();
        #pragma unroll
        for (int p = 0; p < 4; p++) {
            int idx = tid + p * 256;
            int r = idx >> 4, d4 = idx & 15;
            const float* src = &qkv[base + (size_t)(t0 + r) * (3 * Dm) + d4 * 4];
            float4 vk = *(const float4*)(src + Dm);
            float4 vv = *(const float4*)(src + 2 * Dm);
            uint32_t* dk = &Ks[r * KS_STRIDE + d4 * 4];
            dk[0] = f2tf32(vk.x); dk[1] = f2tf32(vk.y);
            dk[2] = f2tf32(vk.z); dk[3] = f2tf32(vk.w);
            uint32_t* dv = &Vs[r * VS_STRIDE + d4 * 4];
            dv[0] = f2tf32(vv.x); dv[1] = f2tf32(vv.y);
            dv[2] = f2tf32(vv.z); dv[3] = f2tf32(vv.w);
        }
        __syncthreads();

        float s[8][4] = {};
        #pragma unroll
        for (int kk = 0; kk < 64; kk += 8) {
            uint32_t a0 = Qs[(qrow + r0) * QS_STRIDE + kk + c0];
            uint32_t a1 = Qs[(qrow + r0 + 8) * QS_STRIDE + kk + c0];
            uint32_t a2 = Qs[(qrow + r0) * QS_STRIDE + kk + c0 + 4];
            uint32_t a3 = Qs[(qrow + r0 + 8) * QS_STRIDE + kk + c0 + 4];
            #pragma unroll
            for (int nt = 0; nt < 8; nt++) {
                uint32_t b0 = Ks[(nt * 8 + r0) * KS_STRIDE + kk + c0];
                uint32_t b1 = Ks[(nt * 8 + r0) * KS_STRIDE + kk + c0 + 4];
                mma_tf32(s[nt], a0, a1, a2, a3, b0, b1);
            }
        }

        const int si0 = q0 + qrow + r0, si1 = si0 + 8;
        float mx0 = -1e30f, mx1 = -1e30f;
        #pragma unroll
        for (int nt = 0; nt < 8; nt++) {
            int tj = t0 + nt * 8 + c0 * 2;
            s[nt][0] = s[nt][0] * 0.125f - slope * fabsf((float)(si0 - tj));
            s[nt][1] = s[nt][1] * 0.125f - slope * fabsf((float)(si0 - tj - 1));
            s[nt][2] = s[nt][2] * 0.125f - slope * fabsf((float)(si1 - tj));
            s[nt][3] = s[nt][3] * 0.125f - slope * fabsf((float)(si1 - tj - 1));
            mx0 = fmaxf(mx0, fmaxf(s[nt][0], s[nt][1]));
            mx1 = fmaxf(mx1, fmaxf(s[nt][2], s[nt][3]));
        }
        mx0 = fmaxf(mx0, __shfl_xor_sync(0xffffffffu, mx0, 1));
        mx0 = fmaxf(mx0, __shfl_xor_sync(0xffffffffu, mx0, 2));
        mx1 = fmaxf(mx1, __shfl_xor_sync(0xffffffffu, mx1, 1));
        mx1 = fmaxf(mx1, __shfl_xor_sync(0xffffffffu, mx1, 2));

        float mn0 = fmaxf(m_i[0], mx0), mn1 = fmaxf(m_i[1], mx1);
        float corr0 = __expf(m_i[0] - mn0), corr1 = __expf(m_i[1] - mn1);
        m_i[0] = mn0; m_i[1] = mn1;

        float sum0 = 0.f, sum1 = 0.f;
        #pragma unroll
        for (int nt = 0; nt < 8; nt++) {
            s[nt][0] = __expf(s[nt][0] - mn0);
            s[nt][1] = __expf(s[nt][1] - mn0);
            s[nt][2] = __expf(s[nt][2] - mn1);
            s[nt][3] = __expf(s[nt][3] - mn1);
            sum0 += s[nt][0] + s[nt][1];
            sum1 += s[nt][2] + s[nt][3];
            uint32_t* d0 = &Ps[(qrow + r0) * PS_STRIDE + nt * 8 + c0 * 2];
            d0[0] = f2tf32(s[nt][0]); d0[1] = f2tf32(s[nt][1]);
            uint32_t* d1 = &Ps[(qrow + r0 + 8) * PS_STRIDE + nt * 8 + c0 * 2];
            d1[0] = f2tf32(s[nt][2]); d1[1] = f2tf32(s[nt][3]);
        }
        sum0 += __shfl_xor_sync(0xffffffffu, sum0, 1);
        sum0 += __shfl_xor_sync(0xffffffffu, sum0, 2);
        sum1 += __shfl_xor_sync(0xffffffffu, sum1, 1);
        sum1 += __shfl_xor_sync(0xffffffffu, sum1, 2);
        l_i[0] = l_i[0] * corr0 + sum0;
        l_i[1] = l_i[1] * corr1 + sum1;
        #pragma unroll
        for (int nt = 0; nt < 8; nt++) {
            o[nt][0] *= corr0; o[nt][1] *= corr0;
            o[nt][2] *= corr1; o[nt][3] *= corr1;
        }
        __syncwarp();

        #pragma unroll
        for (int kk = 0; kk < 64; kk += 8) {
            uint32_t a0 = Ps[(qrow + r0) * PS_STRIDE + kk + c0];
            uint32_t a1 = Ps[(qrow + r0 + 8) * PS_STRIDE + kk + c0];
            uint32_t a2 = Ps[(qrow + r0) * PS_STRIDE + kk + c0 + 4];
            uint32_t a3 = Ps[(qrow + r0 + 8) * PS_STRIDE + kk + c0 + 4];
            #pragma unroll
            for (int nt = 0; nt < 8; nt++) {
                uint32_t b0 = Vs[(kk + c0) * VS_STRIDE + nt * 8 + r0];
                uint32_t b1 = Vs[(kk + c0 + 4) * VS_STRIDE + nt * 8 + r0];
                mma_tf32(o[nt], a0, a1, a2, a3, b0, b1);
            }
        }
    }

    float inv0 = 1.f / l_i[0], inv1 = 1.f / l_i[1];
    size_t obase = ((size_t)b * Sq + q0 + qrow) * Dm + (size_t)h * DH;
    #pragma unroll
    for (int nt = 0; nt < 8; nt++) {
        int d = nt * 8 + c0 * 2;
        attnout[obase + (size_t)r0 * Dm + d]           = o[nt][0] * inv0;
        attnout[obase + (size_t)r0 * Dm + d + 1]       = o[nt][1] * inv0;
        attnout[obase + (size_t)(r0 + 8) * Dm + d]     = o[nt][2] * inv1;
        attnout[obase + (size_t)(r0 + 8) * Dm + d + 1] = o[nt][3] * inv1;
    }
}

// ---------------- host driver ------------------------------------------------
extern "C" void kernel_launch(void* const* d_in, const int* in_sizes, int n_in,
                              void* d_out, int out_size)
{
    const float* x      = (const float*)d_in[0];
    const float* scale1 = (const float*)d_in[1];
    const float* scale2 = (const float*)d_in[2];
    const float* w_qkv  = (const float*)d_in[3];
    const float* b_qkv  = (const float*)d_in[4];
    const float* w_out  = (const float*)d_in[5];
    const float* b_out  = (const float*)d_in[6];
    const float* w1     = (const float*)d_in[7];
    const float* b1     = (const float*)d_in[8];
    const float* w2     = (const float*)d_in[9];
    const float* b2     = (const float*)d_in[10];
    float* out = (float*)d_out;

    void *p_xn, *p_qkv, *p_attnout, *p_x2, *p_h;
    cudaGetSymbolAddress(&p_xn, g_xn);
    cudaGetSymbolAddress(&p_qkv, g_qkv);
    cudaGetSymbolAddress(&p_attnout, g_attnout);
    cudaGetSymbolAddress(&p_x2, g_x2);
    cudaGetSymbolAddress(&p_h, g_h);
    float* xn      = (float*)p_xn;
    float* qkv     = (float*)p_qkv;
    float* attnout = (float*)p_attnout;
    float* x2      = (float*)p_x2;
    float* hbuf    = (float*)p_h;

    cudaFuncSetAttribute(flash_attn, cudaFuncAttributeMaxDynamicSharedMemorySize,
                         FLASH_SMEM);

    // 1) RMSNorm 1
    rmsnorm_kernel<<<Mrows, 256>>>(x, scale1, xn);

    // 2) QKV projection
    gemm_tc<0><<<dim3(3 * Dm / 128, Mrows / 128), 128>>>(
        xn, w_qkv, b_qkv, nullptr, qkv, Mrows, 3 * Dm, Dm);

    // 3-5) fused attention
    flash_attn<<<dim3(Sq / 128, BH), 256, FLASH_SMEM>>>(qkv, attnout);

    // 6) out projection + residual
    gemm_tc<1><<<dim3(Dm / 128, Mrows / 128), 128>>>(
        attnout, w_out, b_out, x, x2, Mrows, Dm, Dm);

    // 7) RMSNorm 2
    rmsnorm_kernel<<<Mrows, 256>>>(x2, scale2, xn);

    // 8) FFN up + GELU
    gemm_tc<2><<<dim3(DFF / 128, Mrows / 128), 128>>>(
        xn, w1, b1, nullptr, hbuf, Mrows, DFF, Dm);

    // 9) FFN down + residual
    gemm_tc<1><<<dim3(Dm / 128, Mrows / 128), 128>>>(
        hbuf, w2, b2, x2, out, Mrows, Dm, DFF);
}

// round 9
// speedup vs baseline: 1.7460x; 1.0510x over previous
#include <cuda_runtime.h>
#include <cuda_bf16.h>
#include <math.h>
#include <stdint.h>

// Problem dims
#define Bz   2
#define Sq   2048
#define Dm   1024
#define Hn   16
#define DH   64
#define DFF  4096
#define Mrows (Bz * Sq)      // 4096
#define BH   (Bz * Hn)       // 32

// ---------------- scratch ----------------------------------------------------
__device__ float g_xn[(size_t)Mrows * Dm];
__device__ float g_qkv[(size_t)Mrows * 3 * Dm];
__device__ float g_attnout[(size_t)Mrows * Dm];
__device__ float g_x2[(size_t)Mrows * Dm];
__device__ float g_h[(size_t)Mrows * DFF];
// RNA-tf32 pre-rounded weights
__device__ float g_wr_qkv[(size_t)Dm * 3 * Dm];
__device__ float g_wr_out[(size_t)Dm * Dm];
__device__ float g_wr1[(size_t)Dm * DFF];
__device__ float g_wr2[(size_t)DFF * Dm];

// ---------------- helpers ----------------------------------------------------
__device__ __forceinline__ uint32_t f2tf32(float f) {
    uint32_t u;
    asm("cvt.rna.tf32.f32 %0, %1;" : "=r"(u) : "f"(f));
    return u;
}
__device__ __forceinline__ float roundtf(float f) {
    return __uint_as_float(f2tf32(f));
}

__device__ __forceinline__ void mma_tf32(float c[4],
    uint32_t a0, uint32_t a1, uint32_t a2, uint32_t a3,
    uint32_t b0, uint32_t b1)
{
    asm volatile(
        "mma.sync.aligned.m16n8k8.row.col.f32.tf32.tf32.f32 "
        "{%0,%1,%2,%3}, {%4,%5,%6,%7}, {%8,%9}, {%0,%1,%2,%3};\n"
        : "+f"(c[0]), "+f"(c[1]), "+f"(c[2]), "+f"(c[3])
        : "r"(a0), "r"(a1), "r"(a2), "r"(a3), "r"(b0), "r"(b1));
}

__device__ __forceinline__ void cp16(uint32_t smem_addr, const void* gptr) {
    asm volatile("cp.async.ca.shared.global [%0], [%1], 16;\n"
                 :: "r"(smem_addr), "l"(gptr));
}
#define CP_COMMIT asm volatile("cp.async.commit_group;\n" ::)
#define CP_WAIT(n) asm volatile("cp.async.wait_group %0;\n" :: "n"(n))

// ---------------- weight pre-rounding (RNA tf32) ------------------------------
__global__ __launch_bounds__(256)
void round_tf32_kernel(const float* __restrict__ src, float* __restrict__ dst,
                       int n4)
{
    int i = blockIdx.x * 256 + threadIdx.x;
    if (i < n4) {
        float4 v = ((const float4*)src)[i];
        v.x = roundtf(v.x); v.y = roundtf(v.y);
        v.z = roundtf(v.z); v.w = roundtf(v.w);
        ((float4*)dst)[i] = v;
    }
}

// ---------------- RMSNorm (output rounded to tf32) ----------------------------
__global__ __launch_bounds__(256)
void rmsnorm_kernel(const float* __restrict__ x, const float* __restrict__ scale,
                    float* __restrict__ out)
{
    int row = blockIdx.x;
    const float* xr = x + (size_t)row * Dm;
    float ss = 0.f;
    #pragma unroll
    for (int i = threadIdx.x; i < Dm; i += 256) { float v = xr[i]; ss += v * v; }
    __shared__ float red[256];
    red[threadIdx.x] = ss; __syncthreads();
    #pragma unroll
    for (int s = 128; s > 0; s >>= 1) {
        if (threadIdx.x < s) red[threadIdx.x] += red[threadIdx.x + s];
        __syncthreads();
    }
    float rms = rsqrtf(red[0] * (1.0f / Dm) + 1e-8f);
    float* orow = out + (size_t)row * Dm;
    #pragma unroll
    for (int i = threadIdx.x; i < Dm; i += 256)
        orow[i] = roundtf(scale[i] * xr[i] * rms);
}

// ---------------- TF32 tensor-core GEMM, cp.async.ca double buffer -----------
// Inputs are pre-rounded RNA tf32 values stored as fp32 (raw bits -> mma).
// EPI: 0 = +bias, 1 = +bias+residual, 2 = +bias, gelu, round output to tf32
// Block tile 128x128, 4 warps, warp tile 64x64, K-chunk 32, 2-stage pipeline.
#define AS_STRIDE 36
#define BS_STRIDE 136
#define AS_ELEMS (128 * AS_STRIDE)
#define BS_ELEMS (32 * BS_STRIDE)
#define GEMM_SMEM ((2 * (AS_ELEMS + BS_ELEMS)) * 4)

template<int EPI>
__global__ __launch_bounds__(128, 2)
void gemm_tc(const float* __restrict__ A, const float* __restrict__ Bm,
             const float* __restrict__ bias, const float* __restrict__ resid,
             float* __restrict__ C, int M, int N, int K)
{
    extern __shared__ __align__(16) float smem[];
    float* Asm = smem;                    // [2][128][36]
    float* Bsm = smem + 2 * AS_ELEMS;     // [2][32][136]

    const int tid = threadIdx.x, warp = tid >> 5, lane = tid & 31;
    const int bm = blockIdx.y * 128, bn = blockIdx.x * 128;
    const int warpM = (warp & 1) * 64, warpN = (warp >> 1) * 64;
    const int r0 = lane >> 2, c0 = lane & 3;
    float c[4][8][4] = {};

    const uint32_t sA = (uint32_t)__cvta_generic_to_shared(Asm);
    const uint32_t sB = (uint32_t)__cvta_generic_to_shared(Bsm);
    const int nk = K >> 5;

    auto load_tile = [&](int i, int buf) {
        const int k0 = i << 5;
        #pragma unroll
        for (int p = 0; p < 8; p++) {
            int idx = tid + p * 128;
            int m = idx >> 3, k4 = idx & 7;
            cp16(sA + (uint32_t)(buf * AS_ELEMS + m * AS_STRIDE + k4 * 4) * 4,
                 &A[(size_t)(bm + m) * K + k0 + k4 * 4]);
        }
        #pragma unroll
        for (int p = 0; p < 8; p++) {
            int idx = tid + p * 128;
            int k = idx >> 5, n4 = idx & 31;
            cp16(sB + (uint32_t)(buf * BS_ELEMS + k * BS_STRIDE + n4 * 4) * 4,
                 &Bm[(size_t)(k0 + k) * N + bn + n4 * 4]);
        }
    };

    load_tile(0, 0);
    CP_COMMIT;

    for (int i = 0; i < nk; i++) {
        const int buf = i & 1;
        if (i + 1 < nk) {
            load_tile(i + 1, buf ^ 1);
            CP_COMMIT;
            CP_WAIT(1);
        } else {
            CP_WAIT(0);
        }
        __syncthreads();

        const float* Ab = Asm + buf * AS_ELEMS;
        const float* Bb = Bsm + buf * BS_ELEMS;
        #pragma unroll
        for (int kk = 0; kk < 32; kk += 8) {
            uint32_t a[4][4], b[8][2];
            #pragma unroll
            for (int mt = 0; mt < 4; mt++) {
                int m = warpM + mt * 16;
                a[mt][0] = __float_as_uint(Ab[(m + r0) * AS_STRIDE + kk + c0]);
                a[mt][1] = __float_as_uint(Ab[(m + r0 + 8) * AS_STRIDE + kk + c0]);
                a[mt][2] = __float_as_uint(Ab[(m + r0) * AS_STRIDE + kk + c0 + 4]);
                a[mt][3] = __float_as_uint(Ab[(m + r0 + 8) * AS_STRIDE + kk + c0 + 4]);
            }
            #pragma unroll
            for (int nt = 0; nt < 8; nt++) {
                int n = warpN + nt * 8 + r0;
                b[nt][0] = __float_as_uint(Bb[(kk + c0) * BS_STRIDE + n]);
                b[nt][1] = __float_as_uint(Bb[(kk + c0 + 4) * BS_STRIDE + n]);
            }
            #pragma unroll
            for (int mt = 0; mt < 4; mt++)
                #pragma unroll
                for (int nt = 0; nt < 8; nt++)
                    mma_tf32(c[mt][nt], a[mt][0], a[mt][1], a[mt][2], a[mt][3],
                             b[nt][0], b[nt][1]);
        }
        __syncthreads();
    }

    #pragma unroll
    for (int mt = 0; mt < 4; mt++) {
        #pragma unroll
        for (int nt = 0; nt < 8; nt++) {
            #pragma unroll
            for (int ci = 0; ci < 4; ci++) {
                int row = bm + warpM + mt * 16 + r0 + ((ci >= 2) ? 8 : 0);
                int col = bn + warpN + nt * 8 + c0 * 2 + (ci & 1);
                float v = c[mt][nt][ci] + bias[col];
                if (EPI == 1) v += resid[(size_t)row * N + col];
                if (EPI == 2) {
                    v = 0.5f * v * (1.0f + erff(v * 0.70710678118654752f));
                    v = roundtf(v);
                }
                C[(size_t)row * N + col] = v;
            }
        }
    }
}

// ---------------- fused flash attention --------------------------------------
#define QS_STRIDE 68
#define KS_STRIDE 68
#define VS_STRIDE 72
#define PS_STRIDE 68
#define FLASH_SMEM ((128 * QS_STRIDE + 64 * KS_STRIDE + 64 * VS_STRIDE + 128 * PS_STRIDE) * 4)

__global__ __launch_bounds__(256, 2)
void flash_attn(const float* __restrict__ qkv, float* __restrict__ attnout)
{
    extern __shared__ uint32_t sm[];
    uint32_t* Qs = sm;
    uint32_t* Ks = Qs + 128 * QS_STRIDE;
    uint32_t* Vs = Ks + 64 * KS_STRIDE;
    uint32_t* Ps = Vs + 64 * VS_STRIDE;

    const int bh = blockIdx.y, b = bh >> 4, h = bh & 15;
    const int q0 = blockIdx.x * 128;
    const int tid = threadIdx.x, warp = tid >> 5, lane = tid & 31;
    const int r0 = lane >> 2, c0 = lane & 3;
    const int qrow = warp * 16;
    const float slope = exp2f(-0.5f * (float)(h + 1));
    const size_t base = (size_t)b * Sq * (3 * Dm) + (size_t)h * DH;

    #pragma unroll
    for (int p = 0; p < 8; p++) {
        int idx = tid + p * 256;
        int r = idx >> 4, d4 = idx & 15;
        float4 v = *(const float4*)&qkv[base + (size_t)(q0 + r) * (3 * Dm) + d4 * 4];
        uint32_t* dst = &Qs[r * QS_STRIDE + d4 * 4];
        dst[0] = f2tf32(v.x); dst[1] = f2tf32(v.y);
        dst[2] = f2tf32(v.z); dst[3] = f2tf32(v.w);
    }

    float m_i[2] = {-1e30f, -1e30f};
    float l_i[2] = {0.f, 0.f};
    float o[8][4] = {};

    for (int t0 = 0; t0 < Sq; t0 += 64) {
        __syncthreads();
        #pragma unroll
        for (int p = 0; p < 4; p++) {
            int idx = tid + p * 256;
            int r = idx >> 4, d4 = idx & 15;
            const float* src = &qkv[base + (size_t)(t0 + r) * (3 * Dm) + d4 * 4];
            float4 vk = *(const float4*)(src + Dm);
            float4 vv = *(const float4*)(src + 2 * Dm);
            uint32_t* dk = &Ks[r * KS_STRIDE + d4 * 4];
            dk[0] = f2tf32(vk.x); dk[1] = f2tf32(vk.y);
            dk[2] = f2tf32(vk.z); dk[3] = f2tf32(vk.w);
            uint32_t* dv = &Vs[r * VS_STRIDE + d4 * 4];
            dv[0] = f2tf32(vv.x); dv[1] = f2tf32(vv.y);
            dv[2] = f2tf32(vv.z); dv[3] = f2tf32(vv.w);
        }
        __syncthreads();

        float s[8][4] = {};
        #pragma unroll
        for (int kk = 0; kk < 64; kk += 8) {
            uint32_t a0 = Qs[(qrow + r0) * QS_STRIDE + kk + c0];
            uint32_t a1 = Qs[(qrow + r0 + 8) * QS_STRIDE + kk + c0];
            uint32_t a2 = Qs[(qrow + r0) * QS_STRIDE + kk + c0 + 4];
            uint32_t a3 = Qs[(qrow + r0 + 8) * QS_STRIDE + kk + c0 + 4];
            #pragma unroll
            for (int nt = 0; nt < 8; nt++) {
                uint32_t b0 = Ks[(nt * 8 + r0) * KS_STRIDE + kk + c0];
                uint32_t b1 = Ks[(nt * 8 + r0) * KS_STRIDE + kk + c0 + 4];
                mma_tf32(s[nt], a0, a1, a2, a3, b0, b1);
            }
        }

        const int si0 = q0 + qrow + r0, si1 = si0 + 8;
        float mx0 = -1e30f, mx1 = -1e30f;
        #pragma unroll
        for (int nt = 0; nt < 8; nt++) {
            int tj = t0 + nt * 8 + c0 * 2;
            s[nt][0] = s[nt][0] * 0.125f - slope * fabsf((float)(si0 - tj));
            s[nt][1] = s[nt][1] * 0.125f - slope * fabsf((float)(si0 - tj - 1));
            s[nt][2] = s[nt][2] * 0.125f - slope * fabsf((float)(si1 - tj));
            s[nt][3] = s[nt][3] * 0.125f - slope * fabsf((float)(si1 - tj - 1));
            mx0 = fmaxf(mx0, fmaxf(s[nt][0], s[nt][1]));
            mx1 = fmaxf(mx1, fmaxf(s[nt][2], s[nt][3]));
        }
        mx0 = fmaxf(mx0, __shfl_xor_sync(0xffffffffu, mx0, 1));
        mx0 = fmaxf(mx0, __shfl_xor_sync(0xffffffffu, mx0, 2));
        mx1 = fmaxf(mx1, __shfl_xor_sync(0xffffffffu, mx1, 1));
        mx1 = fmaxf(mx1, __shfl_xor_sync(0xffffffffu, mx1, 2));

        float mn0 = fmaxf(m_i[0], mx0), mn1 = fmaxf(m_i[1], mx1);
        float corr0 = __expf(m_i[0] - mn0), corr1 = __expf(m_i[1] - mn1);
        m_i[0] = mn0; m_i[1] = mn1;

        float sum0 = 0.f, sum1 = 0.f;
        #pragma unroll
        for (int nt = 0; nt < 8; nt++) {
            s[nt][0] = __expf(s[nt][0] - mn0);
            s[nt][1] = __expf(s[nt][1] - mn0);
            s[nt][2] = __expf(s[nt][2] - mn1);
            s[nt][3] = __expf(s[nt][3] - mn1);
            sum0 += s[nt][0] + s[nt][1];
            sum1 += s[nt][2] + s[nt][3];
            uint32_t* d0 = &Ps[(qrow + r0) * PS_STRIDE + nt * 8 + c0 * 2];
            d0[0] = f2tf32(s[nt][0]); d0[1] = f2tf32(s[nt][1]);
            uint32_t* d1 = &Ps[(qrow + r0 + 8) * PS_STRIDE + nt * 8 + c0 * 2];
            d1[0] = f2tf32(s[nt][2]); d1[1] = f2tf32(s[nt][3]);
        }
        sum0 += __shfl_xor_sync(0xffffffffu, sum0, 1);
        sum0 += __shfl_xor_sync(0xffffffffu, sum0, 2);
        sum1 += __shfl_xor_sync(0xffffffffu, sum1, 1);
        sum1 += __shfl_xor_sync(0xffffffffu, sum1, 2);
        l_i[0] = l_i[0] * corr0 + sum0;
        l_i[1] = l_i[1] * corr1 + sum1;
        #pragma unroll
        for (int nt = 0; nt < 8; nt++) {
            o[nt][0] *= corr0; o[nt][1] *= corr0;
            o[nt][2] *= corr1; o[nt][3] *= corr1;
        }
        __syncwarp();

        #pragma unroll
        for (int kk = 0; kk < 64; kk += 8) {
            uint32_t a0 = Ps[(qrow + r0) * PS_STRIDE + kk + c0];
            uint32_t a1 = Ps[(qrow + r0 + 8) * PS_STRIDE + kk + c0];
            uint32_t a2 = Ps[(qrow + r0) * PS_STRIDE + kk + c0 + 4];
            uint32_t a3 = Ps[(qrow + r0 + 8) * PS_STRIDE + kk + c0 + 4];
            #pragma unroll
            for (int nt = 0; nt < 8; nt++) {
                uint32_t b0 = Vs[(kk + c0) * VS_STRIDE + nt * 8 + r0];
                uint32_t b1 = Vs[(kk + c0 + 4) * VS_STRIDE + nt * 8 + r0];
                mma_tf32(o[nt], a0, a1, a2, a3, b0, b1);
            }
        }
    }

    // outputs rounded to tf32 (next GEMM consumes raw bits)
    float inv0 = 1.f / l_i[0], inv1 = 1.f / l_i[1];
    size_t obase = ((size_t)b * Sq + q0 + qrow) * Dm + (size_t)h * DH;
    #pragma unroll
    for (int nt = 0; nt < 8; nt++) {
        int d = nt * 8 + c0 * 2;
        attnout[obase + (size_t)r0 * Dm + d]           = roundtf(o[nt][0] * inv0);
        attnout[obase + (size_t)r0 * Dm + d + 1]       = roundtf(o[nt][1] * inv0);
        attnout[obase + (size_t)(r0 + 8) * Dm + d]     = roundtf(o[nt][2] * inv1);
        attnout[obase + (size_t)(r0 + 8) * Dm + d + 1] = roundtf(o[nt][3] * inv1);
    }
}

// ---------------- host driver ------------------------------------------------
extern "C" void kernel_launch(void* const* d_in, const int* in_sizes, int n_in,
                              void* d_out, int out_size)
{
    const float* x      = (const float*)d_in[0];
    const float* scale1 = (const float*)d_in[1];
    const float* scale2 = (const float*)d_in[2];
    const float* w_qkv  = (const float*)d_in[3];
    const float* b_qkv  = (const float*)d_in[4];
    const float* w_out  = (const float*)d_in[5];
    const float* b_out  = (const float*)d_in[6];
    const float* w1     = (const float*)d_in[7];
    const float* b1     = (const float*)d_in[8];
    const float* w2     = (const float*)d_in[9];
    const float* b2     = (const float*)d_in[10];
    float* out = (float*)d_out;

    void *p_xn, *p_qkv, *p_attnout, *p_x2, *p_h;
    void *p_wrqkv, *p_wrout, *p_wr1, *p_wr2;
    cudaGetSymbolAddress(&p_xn, g_xn);
    cudaGetSymbolAddress(&p_qkv, g_qkv);
    cudaGetSymbolAddress(&p_attnout, g_attnout);
    cudaGetSymbolAddress(&p_x2, g_x2);
    cudaGetSymbolAddress(&p_h, g_h);
    cudaGetSymbolAddress(&p_wrqkv, g_wr_qkv);
    cudaGetSymbolAddress(&p_wrout, g_wr_out);
    cudaGetSymbolAddress(&p_wr1, g_wr1);
    cudaGetSymbolAddress(&p_wr2, g_wr2);
    float* xn      = (float*)p_xn;
    float* qkv     = (float*)p_qkv;
    float* attnout = (float*)p_attnout;
    float* x2      = (float*)p_x2;
    float* hbuf    = (float*)p_h;
    float* wrqkv   = (float*)p_wrqkv;
    float* wrout   = (float*)p_wrout;
    float* wr1     = (float*)p_wr1;
    float* wr2     = (float*)p_wr2;

    cudaFuncSetAttribute(flash_attn, cudaFuncAttributeMaxDynamicSharedMemorySize,
                         FLASH_SMEM);
    cudaFuncSetAttribute(gemm_tc<0>, cudaFuncAttributeMaxDynamicSharedMemorySize,
                         GEMM_SMEM);
    cudaFuncSetAttribute(gemm_tc<1>, cudaFuncAttributeMaxDynamicSharedMemorySize,
                         GEMM_SMEM);
    cudaFuncSetAttribute(gemm_tc<2>, cudaFuncAttributeMaxDynamicSharedMemorySize,
                         GEMM_SMEM);

    // 0) pre-round weights to RNA tf32
    round_tf32_kernel<<<(Dm * 3 * Dm / 4 + 255) / 256, 256>>>(w_qkv, wrqkv, Dm * 3 * Dm / 4);
    round_tf32_kernel<<<(Dm * Dm / 4 + 255) / 256, 256>>>(w_out, wrout, Dm * Dm / 4);
    round_tf32_kernel<<<(Dm * DFF / 4 + 255) / 256, 256>>>(w1, wr1, Dm * DFF / 4);
    round_tf32_kernel<<<(DFF * Dm / 4 + 255) / 256, 256>>>(w2, wr2, DFF * Dm / 4);

    // 1) RMSNorm 1 (rounds output)
    rmsnorm_kernel<<<Mrows, 256>>>(x, scale1, xn);

    // 2) QKV projection
    gemm_tc<0><<<dim3(3 * Dm / 128, Mrows / 128), 128, GEMM_SMEM>>>(
        xn, wrqkv, b_qkv, nullptr, qkv, Mrows, 3 * Dm, Dm);

    // 3-5) fused attention (rounds attnout)
    flash_attn<<<dim3(Sq / 128, BH), 256, FLASH_SMEM>>>(qkv, attnout);

    // 6) out projection + residual
    gemm_tc<1><<<dim3(Dm / 128, Mrows / 128), 128, GEMM_SMEM>>>(
        attnout, wrout, b_out, x, x2, Mrows, Dm, Dm);

    // 7) RMSNorm 2 (rounds output)
    rmsnorm_kernel<<<Mrows, 256>>>(x2, scale2, xn);

    // 8) FFN up + GELU (rounds hbuf)
    gemm_tc<2><<<dim3(DFF / 128, Mrows / 128), 128, GEMM_SMEM>>>(
        xn, wr1, b1, nullptr, hbuf, Mrows, DFF, Dm);

    // 9) FFN down + residual
    gemm_tc<1><<<dim3(Dm / 128, Mrows / 128), 128, GEMM_SMEM>>>(
        hbuf, wr2, b2, x2, out, Mrows, Dm, DFF);
}

// round 10
// speedup vs baseline: 1.7843x; 1.0219x over previous
#include <cuda_runtime.h>
#include <cuda_bf16.h>
#include <math.h>
#include <stdint.h>

// Problem dims
#define Bz   2
#define Sq   2048
#define Dm   1024
#define Hn   16
#define DH   64
#define DFF  4096
#define Mrows (Bz * Sq)      // 4096
#define BH   (Bz * Hn)       // 32

// ---------------- scratch ----------------------------------------------------
__device__ float g_xn[(size_t)Mrows * Dm];
__device__ float g_qkv[(size_t)Mrows * 3 * Dm];
__device__ float g_attnout[(size_t)Mrows * Dm];
__device__ float g_x2[(size_t)Mrows * Dm];
__device__ float g_h[(size_t)Mrows * DFF];
// transposed + RNA-tf32-rounded weights, [N][K]
__device__ float g_wT_qkv[(size_t)(3 * Dm) * Dm];
__device__ float g_wT_out[(size_t)Dm * Dm];
__device__ float g_wT1[(size_t)DFF * Dm];
__device__ float g_wT2[(size_t)Dm * DFF];

// ---------------- helpers ----------------------------------------------------
__device__ __forceinline__ uint32_t f2tf32(float f) {
    uint32_t u;
    asm("cvt.rna.tf32.f32 %0, %1;" : "=r"(u) : "f"(f));
    return u;
}
__device__ __forceinline__ float roundtf(float f) {
    return __uint_as_float(f2tf32(f));
}

__device__ __forceinline__ void mma_tf32(float c[4],
    uint32_t a0, uint32_t a1, uint32_t a2, uint32_t a3,
    uint32_t b0, uint32_t b1)
{
    asm volatile(
        "mma.sync.aligned.m16n8k8.row.col.f32.tf32.tf32.f32 "
        "{%0,%1,%2,%3}, {%4,%5,%6,%7}, {%8,%9}, {%0,%1,%2,%3};\n"
        : "+f"(c[0]), "+f"(c[1]), "+f"(c[2]), "+f"(c[3])
        : "r"(a0), "r"(a1), "r"(a2), "r"(a3), "r"(b0), "r"(b1));
}

__device__ __forceinline__ void ldsm4(uint32_t& r0, uint32_t& r1,
                                      uint32_t& r2, uint32_t& r3, uint32_t addr)
{
    asm volatile("ldmatrix.sync.aligned.m8n8.x4.shared.b16 {%0,%1,%2,%3}, [%4];"
                 : "=r"(r0), "=r"(r1), "=r"(r2), "=r"(r3) : "r"(addr));
}

__device__ __forceinline__ void cp16(uint32_t smem_addr, const void* gptr) {
    asm volatile("cp.async.ca.shared.global [%0], [%1], 16;\n"
                 :: "r"(smem_addr), "l"(gptr));
}
#define CP_COMMIT asm volatile("cp.async.commit_group;\n" ::)
#define CP_WAIT(n) asm volatile("cp.async.wait_group %0;\n" :: "n"(n))

// ---------------- weight transpose + RNA-tf32 round ---------------------------
// dst[n][k] = round_tf32(src[k][n])
__global__ __launch_bounds__(256)
void transpose_round_kernel(const float* __restrict__ src, float* __restrict__ dst,
                            int K, int N)
{
    __shared__ float t[32][33];
    const int kb = blockIdx.y * 32, nb = blockIdx.x * 32;
    const int tx = threadIdx.x & 31, ty = threadIdx.x >> 5;
    #pragma unroll
    for (int p = 0; p < 4; p++)
        t[ty + p * 8][tx] = src[(size_t)(kb + ty + p * 8) * N + nb + tx];
    __syncthreads();
    #pragma unroll
    for (int p = 0; p < 4; p++)
        dst[(size_t)(nb + ty + p * 8) * K + kb + tx] = roundtf(t[tx][ty + p * 8]);
}

// ---------------- RMSNorm (output rounded to tf32) ----------------------------
__global__ __launch_bounds__(256)
void rmsnorm_kernel(const float* __restrict__ x, const float* __restrict__ scale,
                    float* __restrict__ out)
{
    int row = blockIdx.x;
    const float* xr = x + (size_t)row * Dm;
    float ss = 0.f;
    #pragma unroll
    for (int i = threadIdx.x; i < Dm; i += 256) { float v = xr[i]; ss += v * v; }
    __shared__ float red[256];
    red[threadIdx.x] = ss; __syncthreads();
    #pragma unroll
    for (int s = 128; s > 0; s >>= 1) {
        if (threadIdx.x < s) red[threadIdx.x] += red[threadIdx.x + s];
        __syncthreads();
    }
    float rms = rsqrtf(red[0] * (1.0f / Dm) + 1e-8f);
    float* orow = out + (size_t)row * Dm;
    #pragma unroll
    for (int i = threadIdx.x; i < Dm; i += 256)
        orow[i] = roundtf(scale[i] * xr[i] * rms);
}

// ---------------- TF32 GEMM: ldmatrix fragments + cp.async.ca ----------------
// C[M,N] = A[M,K] @ Bt[N,K]^T, inputs pre-rounded RNA tf32 (raw bits -> mma).
// EPI: 0 = +bias, 1 = +bias+residual, 2 = +bias, gelu (round output)
// Block 128x128, 4 warps, warp tile 64x64, K-chunk 32, 2-stage pipeline.
// Both A and Bt smem tiles: [row][k], stride 36, fragments via ldmatrix.x4.
#define TS 36
#define TILE_ELEMS (128 * TS)
#define GEMM_SMEM (4 * TILE_ELEMS * 4)

template<int EPI>
__global__ __launch_bounds__(128, 2)
void gemm_tc(const float* __restrict__ A, const float* __restrict__ Bt,
             const float* __restrict__ bias, const float* __restrict__ resid,
             float* __restrict__ C, int M, int N, int K)
{
    extern __shared__ __align__(16) float smem[];
    const int tid = threadIdx.x, warp = tid >> 5, lane = tid & 31;
    const int bm = blockIdx.y * 128, bn = blockIdx.x * 128;
    const int warpM = (warp & 1) * 64, warpN = (warp >> 1) * 64;
    const int r0 = lane >> 2, c0 = lane & 3;
    float c[4][8][4] = {};

    const uint32_t sA = (uint32_t)__cvta_generic_to_shared(smem);
    const uint32_t sB = sA + 2 * TILE_ELEMS * 4;

    // ldmatrix per-lane base addresses (byte offsets within buffer 0)
    // A: matrices {rows m..m+7 @kk, m+8..15 @kk, m..m+7 @kk+4, m+8..15 @kk+4}
    const uint32_t aLane = sA +
        (uint32_t)(((warpM + (lane & 15)) * TS + ((lane >> 4) << 2)) * 4);
    // B: matrices {rows n..n+7 @kk, same @kk+4, n+8..15 @kk, same @kk+4}
    const uint32_t bLane = sB +
        (uint32_t)(((warpN + (lane & 7) + ((lane >> 4) << 3)) * TS +
                    (((lane >> 3) & 1) << 2)) * 4);

    const int nk = K >> 5;

    auto load_tile = [&](int i, int buf) {
        const int k0 = i << 5;
        #pragma unroll
        for (int p = 0; p < 8; p++) {
            int idx = tid + p * 128;
            int m = idx >> 3, k4 = idx & 7;
            uint32_t off = (uint32_t)(buf * TILE_ELEMS + m * TS + k4 * 4) * 4;
            cp16(sA + off, &A[(size_t)(bm + m) * K + k0 + k4 * 4]);
            cp16(sB + off, &Bt[(size_t)(bn + m) * K + k0 + k4 * 4]);
        }
    };

    load_tile(0, 0);
    CP_COMMIT;

    for (int i = 0; i < nk; i++) {
        const int buf = i & 1;
        if (i + 1 < nk) {
            load_tile(i + 1, buf ^ 1);
            CP_COMMIT;
            CP_WAIT(1);
        } else {
            CP_WAIT(0);
        }
        __syncthreads();

        const uint32_t bufOff = (uint32_t)(buf * TILE_ELEMS * 4);
        #pragma unroll
        for (int kk = 0; kk < 32; kk += 8) {
            uint32_t a[4][4], b[8][2];
            #pragma unroll
            for (int mt = 0; mt < 4; mt++)
                ldsm4(a[mt][0], a[mt][1], a[mt][2], a[mt][3],
                      aLane + bufOff + (uint32_t)(mt * 16 * TS + kk) * 4);
            #pragma unroll
            for (int np = 0; np < 4; np++)
                ldsm4(b[2 * np][0], b[2 * np][1], b[2 * np + 1][0], b[2 * np + 1][1],
                      bLane + bufOff + (uint32_t)(np * 16 * TS + kk) * 4);
            #pragma unroll
            for (int mt = 0; mt < 4; mt++)
                #pragma unroll
                for (int nt = 0; nt < 8; nt++)
                    mma_tf32(c[mt][nt], a[mt][0], a[mt][1], a[mt][2], a[mt][3],
                             b[nt][0], b[nt][1]);
        }
        __syncthreads();
    }

    #pragma unroll
    for (int mt = 0; mt < 4; mt++) {
        #pragma unroll
        for (int nt = 0; nt < 8; nt++) {
            #pragma unroll
            for (int ci = 0; ci < 4; ci++) {
                int row = bm + warpM + mt * 16 + r0 + ((ci >= 2) ? 8 : 0);
                int col = bn + warpN + nt * 8 + c0 * 2 + (ci & 1);
                float v = c[mt][nt][ci] + bias[col];
                if (EPI == 1) v += resid[(size_t)row * N + col];
                if (EPI == 2) {
                    v = 0.5f * v * (1.0f + erff(v * 0.70710678118654752f));
                    v = roundtf(v);
                }
                C[(size_t)row * N + col] = v;
            }
        }
    }
}

// ---------------- fused flash attention --------------------------------------
#define QS_STRIDE 68
#define KS_STRIDE 68
#define VS_STRIDE 72
#define PS_STRIDE 68
#define FLASH_SMEM ((128 * QS_STRIDE + 64 * KS_STRIDE + 64 * VS_STRIDE + 128 * PS_STRIDE) * 4)

__global__ __launch_bounds__(256, 2)
void flash_attn(const float* __restrict__ qkv, float* __restrict__ attnout)
{
    extern __shared__ uint32_t sm[];
    uint32_t* Qs = sm;
    uint32_t* Ks = Qs + 128 * QS_STRIDE;
    uint32_t* Vs = Ks + 64 * KS_STRIDE;
    uint32_t* Ps = Vs + 64 * VS_STRIDE;

    const int bh = blockIdx.y, b = bh >> 4, h = bh & 15;
    const int q0 = blockIdx.x * 128;
    const int tid = threadIdx.x, warp = tid >> 5, lane = tid & 31;
    const int r0 = lane >> 2, c0 = lane & 3;
    const int qrow = warp * 16;
    const float slope = exp2f(-0.5f * (float)(h + 1));
    const size_t base = (size_t)b * Sq * (3 * Dm) + (size_t)h * DH;

    #pragma unroll
    for (int p = 0; p < 8; p++) {
        int idx = tid + p * 256;
        int r = idx >> 4, d4 = idx & 15;
        float4 v = *(const float4*)&qkv[base + (size_t)(q0 + r) * (3 * Dm) + d4 * 4];
        uint32_t* dst = &Qs[r * QS_STRIDE + d4 * 4];
        dst[0] = f2tf32(v.x); dst[1] = f2tf32(v.y);
        dst[2] = f2tf32(v.z); dst[3] = f2tf32(v.w);
    }

    float m_i[2] = {-1e30f, -1e30f};
    float l_i[2] = {0.f, 0.f};
    float o[8][4] = {};

    for (int t0 = 0; t0 < Sq; t0 += 64) {
        __syncthreads();
        #pragma unroll
        for (int p = 0; p < 4; p++) {
            int idx = tid + p * 256;
            int r = idx >> 4, d4 = idx & 15;
            const float* src = &qkv[base + (size_t)(t0 + r) * (3 * Dm) + d4 * 4];
            float4 vk = *(const float4*)(src + Dm);
            float4 vv = *(const float4*)(src + 2 * Dm);
            uint32_t* dk = &Ks[r * KS_STRIDE + d4 * 4];
            dk[0] = f2tf32(vk.x); dk[1] = f2tf32(vk.y);
            dk[2] = f2tf32(vk.z); dk[3] = f2tf32(vk.w);
            uint32_t* dv = &Vs[r * VS_STRIDE + d4 * 4];
            dv[0] = f2tf32(vv.x); dv[1] = f2tf32(vv.y);
            dv[2] = f2tf32(vv.z); dv[3] = f2tf32(vv.w);
        }
        __syncthreads();

        float s[8][4] = {};
        #pragma unroll
        for (int kk = 0; kk < 64; kk += 8) {
            uint32_t a0 = Qs[(qrow + r0) * QS_STRIDE + kk + c0];
            uint32_t a1 = Qs[(qrow + r0 + 8) * QS_STRIDE + kk + c0];
            uint32_t a2 = Qs[(qrow + r0) * QS_STRIDE + kk + c0 + 4];
            uint32_t a3 = Qs[(qrow + r0 + 8) * QS_STRIDE + kk + c0 + 4];
            #pragma unroll
            for (int nt = 0; nt < 8; nt++) {
                uint32_t b0 = Ks[(nt * 8 + r0) * KS_STRIDE + kk + c0];
                uint32_t b1 = Ks[(nt * 8 + r0) * KS_STRIDE + kk + c0 + 4];
                mma_tf32(s[nt], a0, a1, a2, a3, b0, b1);
            }
        }

        const int si0 = q0 + qrow + r0, si1 = si0 + 8;
        float mx0 = -1e30f, mx1 = -1e30f;
        #pragma unroll
        for (int nt = 0; nt < 8; nt++) {
            int tj = t0 + nt * 8 + c0 * 2;
            s[nt][0] = s[nt][0] * 0.125f - slope * fabsf((float)(si0 - tj));
            s[nt][1] = s[nt][1] * 0.125f - slope * fabsf((float)(si0 - tj - 1));
            s[nt][2] = s[nt][2] * 0.125f - slope * fabsf((float)(si1 - tj));
            s[nt][3] = s[nt][3] * 0.125f - slope * fabsf((float)(si1 - tj - 1));
            mx0 = fmaxf(mx0, fmaxf(s[nt][0], s[nt][1]));
            mx1 = fmaxf(mx1, fmaxf(s[nt][2], s[nt][3]));
        }
        mx0 = fmaxf(mx0, __shfl_xor_sync(0xffffffffu, mx0, 1));
        mx0 = fmaxf(mx0, __shfl_xor_sync(0xffffffffu, mx0, 2));
        mx1 = fmaxf(mx1, __shfl_xor_sync(0xffffffffu, mx1, 1));
        mx1 = fmaxf(mx1, __shfl_xor_sync(0xffffffffu, mx1, 2));

        float mn0 = fmaxf(m_i[0], mx0), mn1 = fmaxf(m_i[1], mx1);
        float corr0 = __expf(m_i[0] - mn0), corr1 = __expf(m_i[1] - mn1);
        m_i[0] = mn0; m_i[1] = mn1;

        float sum0 = 0.f, sum1 = 0.f;
        #pragma unroll
        for (int nt = 0; nt < 8; nt++) {
            s[nt][0] = __expf(s[nt][0] - mn0);
            s[nt][1] = __expf(s[nt][1] - mn0);
            s[nt][2] = __expf(s[nt][2] - mn1);
            s[nt][3] = __expf(s[nt][3] - mn1);
            sum0 += s[nt][0] + s[nt][1];
            sum1 += s[nt][2] + s[nt][3];
            uint32_t* d0 = &Ps[(qrow + r0) * PS_STRIDE + nt * 8 + c0 * 2];
            d0[0] = f2tf32(s[nt][0]); d0[1] = f2tf32(s[nt][1]);
            uint32_t* d1 = &Ps[(qrow + r0 + 8) * PS_STRIDE + nt * 8 + c0 * 2];
            d1[0] = f2tf32(s[nt][2]); d1[1] = f2tf32(s[nt][3]);
        }
        sum0 += __shfl_xor_sync(0xffffffffu, sum0, 1);
        sum0 += __shfl_xor_sync(0xffffffffu, sum0, 2);
        sum1 += __shfl_xor_sync(0xffffffffu, sum1, 1);
        sum1 += __shfl_xor_sync(0xffffffffu, sum1, 2);
        l_i[0] = l_i[0] * corr0 + sum0;
        l_i[1] = l_i[1] * corr1 + sum1;
        #pragma unroll
        for (int nt = 0; nt < 8; nt++) {
            o[nt][0] *= corr0; o[nt][1] *= corr0;
            o[nt][2] *= corr1; o[nt][3] *= corr1;
        }
        __syncwarp();

        #pragma unroll
        for (int kk = 0; kk < 64; kk += 8) {
            uint32_t a0 = Ps[(qrow + r0) * PS_STRIDE + kk + c0];
            uint32_t a1 = Ps[(qrow + r0 + 8) * PS_STRIDE + kk + c0];
            uint32_t a2 = Ps[(qrow + r0) * PS_STRIDE + kk + c0 + 4];
            uint32_t a3 = Ps[(qrow + r0 + 8) * PS_STRIDE + kk + c0 + 4];
            #pragma unroll
            for (int nt = 0; nt < 8; nt++) {
                uint32_t b0 = Vs[(kk + c0) * VS_STRIDE + nt * 8 + r0];
                uint32_t b1 = Vs[(kk + c0 + 4) * VS_STRIDE + nt * 8 + r0];
                mma_tf32(o[nt], a0, a1, a2, a3, b0, b1);
            }
        }
    }

    float inv0 = 1.f / l_i[0], inv1 = 1.f / l_i[1];
    size_t obase = ((size_t)b * Sq + q0 + qrow) * Dm + (size_t)h * DH;
    #pragma unroll
    for (int nt = 0; nt < 8; nt++) {
        int d = nt * 8 + c0 * 2;
        attnout[obase + (size_t)r0 * Dm + d]           = roundtf(o[nt][0] * inv0);
        attnout[obase + (size_t)r0 * Dm + d + 1]       = roundtf(o[nt][1] * inv0);
        attnout[obase + (size_t)(r0 + 8) * Dm + d]     = roundtf(o[nt][2] * inv1);
        attnout[obase + (size_t)(r0 + 8) * Dm + d + 1] = roundtf(o[nt][3] * inv1);
    }
}

// ---------------- host driver ------------------------------------------------
extern "C" void kernel_launch(void* const* d_in, const int* in_sizes, int n_in,
                              void* d_out, int out_size)
{
    const float* x      = (const float*)d_in[0];
    const float* scale1 = (const float*)d_in[1];
    const float* scale2 = (const float*)d_in[2];
    const float* w_qkv  = (const float*)d_in[3];
    const float* b_qkv  = (const float*)d_in[4];
    const float* w_out  = (const float*)d_in[5];
    const float* b_out  = (const float*)d_in[6];
    const float* w1     = (const float*)d_in[7];
    const float* b1     = (const float*)d_in[8];
    const float* w2     = (const float*)d_in[9];
    const float* b2     = (const float*)d_in[10];
    float* out = (float*)d_out;

    void *p_xn, *p_qkv, *p_attnout, *p_x2, *p_h;
    void *p_wqkv, *p_wout, *p_w1, *p_w2;
    cudaGetSymbolAddress(&p_xn, g_xn);
    cudaGetSymbolAddress(&p_qkv, g_qkv);
    cudaGetSymbolAddress(&p_attnout, g_attnout);
    cudaGetSymbolAddress(&p_x2, g_x2);
    cudaGetSymbolAddress(&p_h, g_h);
    cudaGetSymbolAddress(&p_wqkv, g_wT_qkv);
    cudaGetSymbolAddress(&p_wout, g_wT_out);
    cudaGetSymbolAddress(&p_w1, g_wT1);
    cudaGetSymbolAddress(&p_w2, g_wT2);
    float* xn      = (float*)p_xn;
    float* qkv     = (float*)p_qkv;
    float* attnout = (float*)p_attnout;
    float* x2      = (float*)p_x2;
    float* hbuf    = (float*)p_h;
    float* wTqkv   = (float*)p_wqkv;
    float* wTout   = (float*)p_wout;
    float* wT1     = (float*)p_w1;
    float* wT2     = (float*)p_w2;

    cudaFuncSetAttribute(flash_attn, cudaFuncAttributeMaxDynamicSharedMemorySize,
                         FLASH_SMEM);
    cudaFuncSetAttribute(gemm_tc<0>, cudaFuncAttributeMaxDynamicSharedMemorySize,
                         GEMM_SMEM);
    cudaFuncSetAttribute(gemm_tc<1>, cudaFuncAttributeMaxDynamicSharedMemorySize,
                         GEMM_SMEM);
    cudaFuncSetAttribute(gemm_tc<2>, cudaFuncAttributeMaxDynamicSharedMemorySize,
                         GEMM_SMEM);

    // 0) transpose + RNA-round weights -> [N][K]
    transpose_round_kernel<<<dim3(3 * Dm / 32, Dm / 32), 256>>>(w_qkv, wTqkv, Dm, 3 * Dm);
    transpose_round_kernel<<<dim3(Dm / 32, Dm / 32), 256>>>(w_out, wTout, Dm, Dm);
    transpose_round_kernel<<<dim3(DFF / 32, Dm / 32), 256>>>(w1, wT1, Dm, DFF);
    transpose_round_kernel<<<dim3(Dm / 32, DFF / 32), 256>>>(w2, wT2, DFF, Dm);

    // 1) RMSNorm 1 (rounds output)
    rmsnorm_kernel<<<Mrows, 256>>>(x, scale1, xn);

    // 2) QKV projection
    gemm_tc<0><<<dim3(3 * Dm / 128, Mrows / 128), 128, GEMM_SMEM>>>(
        xn, wTqkv, b_qkv, nullptr, qkv, Mrows, 3 * Dm, Dm);

    // 3-5) fused attention (rounds attnout)
    flash_attn<<<dim3(Sq / 128, BH), 256, FLASH_SMEM>>>(qkv, attnout);

    // 6) out projection + residual
    gemm_tc<1><<<dim3(Dm / 128, Mrows / 128), 128, GEMM_SMEM>>>(
        attnout, wTout, b_out, x, x2, Mrows, Dm, Dm);

    // 7) RMSNorm 2 (rounds output)
    rmsnorm_kernel<<<Mrows, 256>>>(x2, scale2, xn);

    // 8) FFN up + GELU (rounds hbuf)
    gemm_tc<2><<<dim3(DFF / 128, Mrows / 128), 128, GEMM_SMEM>>>(
        xn, wT1, b1, nullptr, hbuf, Mrows, DFF, Dm);

    // 9) FFN down + residual
    gemm_tc<1><<<dim3(Dm / 128, Mrows / 128), 128, GEMM_SMEM>>>(
        hbuf, wT2, b2, x2, out, Mrows, Dm, DFF);
}

// round 11
// speedup vs baseline: 2.4341x; 1.3642x over previous
#include <cuda_runtime.h>
#include <cuda_fp16.h>
#include <math.h>
#include <stdint.h>

// Problem dims
#define Bz   2
#define Sq   2048
#define Dm   1024
#define Hn   16
#define DH   64
#define DFF  4096
#define Mrows (Bz * Sq)      // 4096
#define BH   (Bz * Hn)       // 32

// ---------------- scratch ----------------------------------------------------
__device__ __half g_xn[(size_t)Mrows * Dm];
__device__ float  g_qkv[(size_t)Mrows * 3 * Dm];
__device__ __half g_attnout[(size_t)Mrows * Dm];
__device__ float  g_x2[(size_t)Mrows * Dm];
__device__ __half g_h[(size_t)Mrows * DFF];
// transposed + fp16 weights, [N][K]
__device__ __half g_wT_qkv[(size_t)(3 * Dm) * Dm];
__device__ __half g_wT_out[(size_t)Dm * Dm];
__device__ __half g_wT1[(size_t)DFF * Dm];
__device__ __half g_wT2[(size_t)Dm * DFF];

// ---------------- helpers ----------------------------------------------------
__device__ __forceinline__ uint32_t f2tf32(float f) {
    uint32_t u;
    asm("cvt.rna.tf32.f32 %0, %1;" : "=r"(u) : "f"(f));
    return u;
}

__device__ __forceinline__ void mma_tf32(float c[4],
    uint32_t a0, uint32_t a1, uint32_t a2, uint32_t a3,
    uint32_t b0, uint32_t b1)
{
    asm volatile(
        "mma.sync.aligned.m16n8k8.row.col.f32.tf32.tf32.f32 "
        "{%0,%1,%2,%3}, {%4,%5,%6,%7}, {%8,%9}, {%0,%1,%2,%3};\n"
        : "+f"(c[0]), "+f"(c[1]), "+f"(c[2]), "+f"(c[3])
        : "r"(a0), "r"(a1), "r"(a2), "r"(a3), "r"(b0), "r"(b1));
}

__device__ __forceinline__ void mma_f16(float c[4],
    uint32_t a0, uint32_t a1, uint32_t a2, uint32_t a3,
    uint32_t b0, uint32_t b1)
{
    asm volatile(
        "mma.sync.aligned.m16n8k16.row.col.f32.f16.f16.f32 "
        "{%0,%1,%2,%3}, {%4,%5,%6,%7}, {%8,%9}, {%0,%1,%2,%3};\n"
        : "+f"(c[0]), "+f"(c[1]), "+f"(c[2]), "+f"(c[3])
        : "r"(a0), "r"(a1), "r"(a2), "r"(a3), "r"(b0), "r"(b1));
}

__device__ __forceinline__ void ldsm4(uint32_t& r0, uint32_t& r1,
                                      uint32_t& r2, uint32_t& r3, uint32_t addr)
{
    asm volatile("ldmatrix.sync.aligned.m8n8.x4.shared.b16 {%0,%1,%2,%3}, [%4];"
                 : "=r"(r0), "=r"(r1), "=r"(r2), "=r"(r3) : "r"(addr));
}

__device__ __forceinline__ void cp16(uint32_t smem_addr, const void* gptr) {
    asm volatile("cp.async.ca.shared.global [%0], [%1], 16;\n"
                 :: "r"(smem_addr), "l"(gptr));
}
#define CP_COMMIT asm volatile("cp.async.commit_group;\n" ::)
#define CP_WAIT(n) asm volatile("cp.async.wait_group %0;\n" :: "n"(n))

__device__ __forceinline__ void store_out(float* p, float v) { *p = v; }
__device__ __forceinline__ void store_out(__half* p, float v) { *p = __float2half_rn(v); }

// ---------------- weight transpose + fp16 convert -----------------------------
// dst[n][k] = half(src[k][n])
__global__ __launch_bounds__(256)
void transpose_half_kernel(const float* __restrict__ src, __half* __restrict__ dst,
                           int K, int N)
{
    __shared__ float t[32][33];
    const int kb = blockIdx.y * 32, nb = blockIdx.x * 32;
    const int tx = threadIdx.x & 31, ty = threadIdx.x >> 5;
    #pragma unroll
    for (int p = 0; p < 4; p++)
        t[ty + p * 8][tx] = src[(size_t)(kb + ty + p * 8) * N + nb + tx];
    __syncthreads();
    #pragma unroll
    for (int p = 0; p < 4; p++)
        dst[(size_t)(nb + ty + p * 8) * K + kb + tx] = __float2half_rn(t[tx][ty + p * 8]);
}

// ---------------- RMSNorm (fp16 output) ---------------------------------------
__global__ __launch_bounds__(256)
void rmsnorm_kernel(const float* __restrict__ x, const float* __restrict__ scale,
                    __half* __restrict__ out)
{
    int row = blockIdx.x;
    const float* xr = x + (size_t)row * Dm;
    float ss = 0.f;
    #pragma unroll
    for (int i = threadIdx.x; i < Dm; i += 256) { float v = xr[i]; ss += v * v; }
    __shared__ float red[256];
    red[threadIdx.x] = ss; __syncthreads();
    #pragma unroll
    for (int s = 128; s > 0; s >>= 1) {
        if (threadIdx.x < s) red[threadIdx.x] += red[threadIdx.x + s];
        __syncthreads();
    }
    float rms = rsqrtf(red[0] * (1.0f / Dm) + 1e-8f);
    __half* orow = out + (size_t)row * Dm;
    #pragma unroll
    for (int i = threadIdx.x; i < Dm; i += 256)
        orow[i] = __float2half_rn(scale[i] * xr[i] * rms);
}

// ---------------- FP16 GEMM: ldmatrix + cp.async, single-sync pipeline --------
// C[M,N] = A[M,K] @ Bt[N,K]^T, A/Bt fp16, fp32 accumulate.
// EPI: 0 = +bias, 1 = +bias+residual, 2 = +bias, gelu
// Block 128x128, 4 warps, warp tile 64x64, K-chunk 64, 2-stage pipeline.
// smem tiles [row][k] fp16, row stride 72 halves (144B) -> ldsm conflict-free.
#define TSH 72
#define TILE_H (128 * TSH)
#define GEMM_SMEM (4 * TILE_H * 2)

template<int EPI, typename TO>
__global__ __launch_bounds__(128, 2)
void gemm_tc(const __half* __restrict__ A, const __half* __restrict__ Bt,
             const float* __restrict__ bias, const float* __restrict__ resid,
             TO* __restrict__ C, int M, int N, int K)
{
    extern __shared__ __align__(16) char smemc[];
    const int tid = threadIdx.x, warp = tid >> 5, lane = tid & 31;
    const int bm = blockIdx.y * 128, bn = blockIdx.x * 128;
    const int warpM = (warp & 1) * 64, warpN = (warp >> 1) * 64;
    const int r0 = lane >> 2, c0 = lane & 3;
    float c[4][8][4] = {};

    const uint32_t sA = (uint32_t)__cvta_generic_to_shared(smemc);
    const uint32_t sB = sA + 2 * TILE_H * 2;

    // ldmatrix per-lane base byte addresses (buffer 0)
    const uint32_t aLane = sA +
        (uint32_t)((warpM + (lane & 15)) * TSH * 2 + ((lane >> 4) << 4));
    const uint32_t bLane = sB +
        (uint32_t)((warpN + (lane & 7) + ((lane >> 4) << 3)) * TSH * 2 +
                   (((lane >> 3) & 1) << 4));

    const int nk = K >> 6;

    auto load_tile = [&](int i, int buf) {
        const int k0 = i << 6;
        #pragma unroll
        for (int p = 0; p < 8; p++) {
            int idx = tid + p * 128;
            int m = idx >> 3, seg = idx & 7;
            uint32_t off = (uint32_t)(buf * TILE_H * 2 + m * TSH * 2 + seg * 16);
            cp16(sA + off, &A[(size_t)(bm + m) * K + k0 + seg * 8]);
            cp16(sB + off, &Bt[(size_t)(bn + m) * K + k0 + seg * 8]);
        }
    };

    load_tile(0, 0);
    CP_COMMIT;

    for (int i = 0; i < nk; i++) {
        const int buf = i & 1;
        CP_WAIT(0);
        __syncthreads();
        if (i + 1 < nk) {
            load_tile(i + 1, buf ^ 1);
            CP_COMMIT;
        }
        const uint32_t bufOff = (uint32_t)(buf * TILE_H * 2);
        #pragma unroll
        for (int kk = 0; kk < 64; kk += 16) {
            uint32_t a[4][4], b[8][2];
            #pragma unroll
            for (int mt = 0; mt < 4; mt++)
                ldsm4(a[mt][0], a[mt][1], a[mt][2], a[mt][3],
                      aLane + bufOff + (uint32_t)(mt * 16 * TSH * 2 + kk * 2));
            #pragma unroll
            for (int np = 0; np < 4; np++)
                ldsm4(b[2 * np][0], b[2 * np][1], b[2 * np + 1][0], b[2 * np + 1][1],
                      bLane + bufOff + (uint32_t)(np * 16 * TSH * 2 + kk * 2));
            #pragma unroll
            for (int mt = 0; mt < 4; mt++)
                #pragma unroll
                for (int nt = 0; nt < 8; nt++)
                    mma_f16(c[mt][nt], a[mt][0], a[mt][1], a[mt][2], a[mt][3],
                            b[nt][0], b[nt][1]);
        }
    }

    #pragma unroll
    for (int mt = 0; mt < 4; mt++) {
        #pragma unroll
        for (int nt = 0; nt < 8; nt++) {
            #pragma unroll
            for (int ci = 0; ci < 4; ci++) {
                int row = bm + warpM + mt * 16 + r0 + ((ci >= 2) ? 8 : 0);
                int col = bn + warpN + nt * 8 + c0 * 2 + (ci & 1);
                float v = c[mt][nt][ci] + bias[col];
                if (EPI == 1) v += resid[(size_t)row * N + col];
                if (EPI == 2) v = 0.5f * v * (1.0f + erff(v * 0.70710678118654752f));
                store_out(&C[(size_t)row * N + col], v);
            }
        }
    }
}

// ---------------- fused flash attention (tf32, fp16 output) -------------------
#define QS_STRIDE 68
#define KS_STRIDE 68
#define VS_STRIDE 72
#define PS_STRIDE 68
#define FLASH_SMEM ((128 * QS_STRIDE + 64 * KS_STRIDE + 64 * VS_STRIDE + 128 * PS_STRIDE) * 4)

__global__ __launch_bounds__(256, 2)
void flash_attn(const float* __restrict__ qkv, __half* __restrict__ attnout)
{
    extern __shared__ uint32_t sm[];
    uint32_t* Qs = sm;
    uint32_t* Ks = Qs + 128 * QS_STRIDE;
    uint32_t* Vs = Ks + 64 * KS_STRIDE;
    uint32_t* Ps = Vs + 64 * VS_STRIDE;

    const int bh = blockIdx.y, b = bh >> 4, h = bh & 15;
    const int q0 = blockIdx.x * 128;
    const int tid = threadIdx.x, warp = tid >> 5, lane = tid & 31;
    const int r0 = lane >> 2, c0 = lane & 3;
    const int qrow = warp * 16;
    const float slope = exp2f(-0.5f * (float)(h + 1));
    const size_t base = (size_t)b * Sq * (3 * Dm) + (size_t)h * DH;

    #pragma unroll
    for (int p = 0; p < 8; p++) {
        int idx = tid + p * 256;
        int r = idx >> 4, d4 = idx & 15;
        float4 v = *(const float4*)&qkv[base + (size_t)(q0 + r) * (3 * Dm) + d4 * 4];
        uint32_t* dst = &Qs[r * QS_STRIDE + d4 * 4];
        dst[0] = f2tf32(v.x); dst[1] = f2tf32(v.y);
        dst[2] = f2tf32(v.z); dst[3] = f2tf32(v.w);
    }

    float m_i[2] = {-1e30f, -1e30f};
    float l_i[2] = {0.f, 0.f};
    float o[8][4] = {};

    for (int t0 = 0; t0 < Sq; t0 += 64) {
        __syncthreads();
        #pragma unroll
        for (int p = 0; p < 4; p++) {
            int idx = tid + p * 256;
            int r = idx >> 4, d4 = idx & 15;
            const float* src = &qkv[base + (size_t)(t0 + r) * (3 * Dm) + d4 * 4];
            float4 vk = *(const float4*)(src + Dm);
            float4 vv = *(const float4*)(src + 2 * Dm);
            uint32_t* dk = &Ks[r * KS_STRIDE + d4 * 4];
            dk[0] = f2tf32(vk.x); dk[1] = f2tf32(vk.y);
            dk[2] = f2tf32(vk.z); dk[3] = f2tf32(vk.w);
            uint32_t* dv = &Vs[r * VS_STRIDE + d4 * 4];
            dv[0] = f2tf32(vv.x); dv[1] = f2tf32(vv.y);
            dv[2] = f2tf32(vv.z); dv[3] = f2tf32(vv.w);
        }
        __syncthreads();

        float s[8][4] = {};
        #pragma unroll
        for (int kk = 0; kk < 64; kk += 8) {
            uint32_t a0 = Qs[(qrow + r0) * QS_STRIDE + kk + c0];
            uint32_t a1 = Qs[(qrow + r0 + 8) * QS_STRIDE + kk + c0];
            uint32_t a2 = Qs[(qrow + r0) * QS_STRIDE + kk + c0 + 4];
            uint32_t a3 = Qs[(qrow + r0 + 8) * QS_STRIDE + kk + c0 + 4];
            #pragma unroll
            for (int nt = 0; nt < 8; nt++) {
                uint32_t b0 = Ks[(nt * 8 + r0) * KS_STRIDE + kk + c0];
                uint32_t b1 = Ks[(nt * 8 + r0) * KS_STRIDE + kk + c0 + 4];
                mma_tf32(s[nt], a0, a1, a2, a3, b0, b1);
            }
        }

        const int si0 = q0 + qrow + r0, si1 = si0 + 8;
        float mx0 = -1e30f, mx1 = -1e30f;
        #pragma unroll
        for (int nt = 0; nt < 8; nt++) {
            int tj = t0 + nt * 8 + c0 * 2;
            s[nt][0] = s[nt][0] * 0.125f - slope * fabsf((float)(si0 - tj));
            s[nt][1] = s[nt][1] * 0.125f - slope * fabsf((float)(si0 - tj - 1));
            s[nt][2] = s[nt][2] * 0.125f - slope * fabsf((float)(si1 - tj));
            s[nt][3] = s[nt][3] * 0.125f - slope * fabsf((float)(si1 - tj - 1));
            mx0 = fmaxf(mx0, fmaxf(s[nt][0], s[nt][1]));
            mx1 = fmaxf(mx1, fmaxf(s[nt][2], s[nt][3]));
        }
        mx0 = fmaxf(mx0, __shfl_xor_sync(0xffffffffu, mx0, 1));
        mx0 = fmaxf(mx0, __shfl_xor_sync(0xffffffffu, mx0, 2));
        mx1 = fmaxf(mx1, __shfl_xor_sync(0xffffffffu, mx1, 1));
        mx1 = fmaxf(mx1, __shfl_xor_sync(0xffffffffu, mx1, 2));

        float mn0 = fmaxf(m_i[0], mx0), mn1 = fmaxf(m_i[1], mx1);
        float corr0 = __expf(m_i[0] - mn0), corr1 = __expf(m_i[1] - mn1);
        m_i[0] = mn0; m_i[1] = mn1;

        float sum0 = 0.f, sum1 = 0.f;
        #pragma unroll
        for (int nt = 0; nt < 8; nt++) {
            s[nt][0] = __expf(s[nt][0] - mn0);
            s[nt][1] = __expf(s[nt][1] - mn0);
            s[nt][2] = __expf(s[nt][2] - mn1);
            s[nt][3] = __expf(s[nt][3] - mn1);
            sum0 += s[nt][0] + s[nt][1];
            sum1 += s[nt][2] + s[nt][3];
            uint32_t* d0 = &Ps[(qrow + r0) * PS_STRIDE + nt * 8 + c0 * 2];
            d0[0] = f2tf32(s[nt][0]); d0[1] = f2tf32(s[nt][1]);
            uint32_t* d1 = &Ps[(qrow + r0 + 8) * PS_STRIDE + nt * 8 + c0 * 2];
            d1[0] = f2tf32(s[nt][2]); d1[1] = f2tf32(s[nt][3]);
        }
        sum0 += __shfl_xor_sync(0xffffffffu, sum0, 1);
        sum0 += __shfl_xor_sync(0xffffffffu, sum0, 2);
        sum1 += __shfl_xor_sync(0xffffffffu, sum1, 1);
        sum1 += __shfl_xor_sync(0xffffffffu, sum1, 2);
        l_i[0] = l_i[0] * corr0 + sum0;
        l_i[1] = l_i[1] * corr1 + sum1;
        #pragma unroll
        for (int nt = 0; nt < 8; nt++) {
            o[nt][0] *= corr0; o[nt][1] *= corr0;
            o[nt][2] *= corr1; o[nt][3] *= corr1;
        }
        __syncwarp();

        #pragma unroll
        for (int kk = 0; kk < 64; kk += 8) {
            uint32_t a0 = Ps[(qrow + r0) * PS_STRIDE + kk + c0];
            uint32_t a1 = Ps[(qrow + r0 + 8) * PS_STRIDE + kk + c0];
            uint32_t a2 = Ps[(qrow + r0) * PS_STRIDE + kk + c0 + 4];
            uint32_t a3 = Ps[(qrow + r0 + 8) * PS_STRIDE + kk + c0 + 4];
            #pragma unroll
            for (int nt = 0; nt < 8; nt++) {
                uint32_t b0 = Vs[(kk + c0) * VS_STRIDE + nt * 8 + r0];
                uint32_t b1 = Vs[(kk + c0 + 4) * VS_STRIDE + nt * 8 + r0];
                mma_tf32(o[nt], a0, a1, a2, a3, b0, b1);
            }
        }
    }

    float inv0 = 1.f / l_i[0], inv1 = 1.f / l_i[1];
    size_t obase = ((size_t)b * Sq + q0 + qrow) * Dm + (size_t)h * DH;
    #pragma unroll
    for (int nt = 0; nt < 8; nt++) {
        int d = nt * 8 + c0 * 2;
        attnout[obase + (size_t)r0 * Dm + d]           = __float2half_rn(o[nt][0] * inv0);
        attnout[obase + (size_t)r0 * Dm + d + 1]       = __float2half_rn(o[nt][1] * inv0);
        attnout[obase + (size_t)(r0 + 8) * Dm + d]     = __float2half_rn(o[nt][2] * inv1);
        attnout[obase + (size_t)(r0 + 8) * Dm + d + 1] = __float2half_rn(o[nt][3] * inv1);
    }
}

// ---------------- host driver ------------------------------------------------
extern "C" void kernel_launch(void* const* d_in, const int* in_sizes, int n_in,
                              void* d_out, int out_size)
{
    const float* x      = (const float*)d_in[0];
    const float* scale1 = (const float*)d_in[1];
    const float* scale2 = (const float*)d_in[2];
    const float* w_qkv  = (const float*)d_in[3];
    const float* b_qkv  = (const float*)d_in[4];
    const float* w_out  = (const float*)d_in[5];
    const float* b_out  = (const float*)d_in[6];
    const float* w1     = (const float*)d_in[7];
    const float* b1     = (const float*)d_in[8];
    const float* w2     = (const float*)d_in[9];
    const float* b2     = (const float*)d_in[10];
    float* out = (float*)d_out;

    void *p_xn, *p_qkv, *p_attnout, *p_x2, *p_h;
    void *p_wqkv, *p_wout, *p_w1, *p_w2;
    cudaGetSymbolAddress(&p_xn, g_xn);
    cudaGetSymbolAddress(&p_qkv, g_qkv);
    cudaGetSymbolAddress(&p_attnout, g_attnout);
    cudaGetSymbolAddress(&p_x2, g_x2);
    cudaGetSymbolAddress(&p_h, g_h);
    cudaGetSymbolAddress(&p_wqkv, g_wT_qkv);
    cudaGetSymbolAddress(&p_wout, g_wT_out);
    cudaGetSymbolAddress(&p_w1, g_wT1);
    cudaGetSymbolAddress(&p_w2, g_wT2);
    __half* xn      = (__half*)p_xn;
    float*  qkv     = (float*)p_qkv;
    __half* attnout = (__half*)p_attnout;
    float*  x2      = (float*)p_x2;
    __half* hbuf    = (__half*)p_h;
    __half* wTqkv   = (__half*)p_wqkv;
    __half* wTout   = (__half*)p_wout;
    __half* wT1     = (__half*)p_w1;
    __half* wT2     = (__half*)p_w2;

    cudaFuncSetAttribute(flash_attn, cudaFuncAttributeMaxDynamicSharedMemorySize,
                         FLASH_SMEM);
    cudaFuncSetAttribute(gemm_tc<0, float>, cudaFuncAttributeMaxDynamicSharedMemorySize,
                         GEMM_SMEM);
    cudaFuncSetAttribute(gemm_tc<1, float>, cudaFuncAttributeMaxDynamicSharedMemorySize,
                         GEMM_SMEM);
    cudaFuncSetAttribute(gemm_tc<2, __half>, cudaFuncAttributeMaxDynamicSharedMemorySize,
                         GEMM_SMEM);

    // 0) transpose + fp16 weights -> [N][K]
    transpose_half_kernel<<<dim3(3 * Dm / 32, Dm / 32), 256>>>(w_qkv, wTqkv, Dm, 3 * Dm);
    transpose_half_kernel<<<dim3(Dm / 32, Dm / 32), 256>>>(w_out, wTout, Dm, Dm);
    transpose_half_kernel<<<dim3(DFF / 32, Dm / 32), 256>>>(w1, wT1, Dm, DFF);
    transpose_half_kernel<<<dim3(Dm / 32, DFF / 32), 256>>>(w2, wT2, DFF, Dm);

    // 1) RMSNorm 1 -> fp16 xn
    rmsnorm_kernel<<<Mrows, 256>>>(x, scale1, xn);

    // 2) QKV projection (fp16 in, fp32 out)
    gemm_tc<0, float><<<dim3(3 * Dm / 128, Mrows / 128), 128, GEMM_SMEM>>>(
        xn, wTqkv, b_qkv, nullptr, qkv, Mrows, 3 * Dm, Dm);

    // 3-5) fused attention -> fp16 attnout
    flash_attn<<<dim3(Sq / 128, BH), 256, FLASH_SMEM>>>(qkv, attnout);

    // 6) out projection + residual (fp32 out)
    gemm_tc<1, float><<<dim3(Dm / 128, Mrows / 128), 128, GEMM_SMEM>>>(
        attnout, wTout, b_out, x, x2, Mrows, Dm, Dm);

    // 7) RMSNorm 2 -> fp16 xn
    rmsnorm_kernel<<<Mrows, 256>>>(x2, scale2, xn);

    // 8) FFN up + GELU -> fp16 hbuf
    gemm_tc<2, __half><<<dim3(DFF / 128, Mrows / 128), 128, GEMM_SMEM>>>(
        xn, wT1, b1, nullptr, hbuf, Mrows, DFF, Dm);

    // 9) FFN down + residual (fp32 out)
    gemm_tc<1, float><<<dim3(Dm / 128, Mrows / 128), 128, GEMM_SMEM>>>(
        hbuf, wT2, b2, x2, out, Mrows, Dm, DFF);
}

// round 12
// speedup vs baseline: 3.0487x; 1.2525x over previous
#include <cuda_runtime.h>
#include <cuda_fp16.h>
#include <math.h>
#include <stdint.h>

// Problem dims
#define Bz   2
#define Sq   2048
#define Dm   1024
#define Hn   16
#define DH   64
#define DFF  4096
#define Mrows (Bz * Sq)      // 4096
#define BH   (Bz * Hn)       // 32

// ---------------- scratch ----------------------------------------------------
__device__ __half g_xn[(size_t)Mrows * Dm];
__device__ float  g_qkv[(size_t)Mrows * 3 * Dm];
__device__ __half g_attnout[(size_t)Mrows * Dm];
__device__ float  g_x2[(size_t)Mrows * Dm];
__device__ __half g_h[(size_t)Mrows * DFF];
// transposed + fp16 weights, [N][K]
__device__ __half g_wT_qkv[(size_t)(3 * Dm) * Dm];
__device__ __half g_wT_out[(size_t)Dm * Dm];
__device__ __half g_wT1[(size_t)DFF * Dm];
__device__ __half g_wT2[(size_t)Dm * DFF];

// ---------------- helpers ----------------------------------------------------
__device__ __forceinline__ void mma_f16(float c[4],
    uint32_t a0, uint32_t a1, uint32_t a2, uint32_t a3,
    uint32_t b0, uint32_t b1)
{
    asm volatile(
        "mma.sync.aligned.m16n8k16.row.col.f32.f16.f16.f32 "
        "{%0,%1,%2,%3}, {%4,%5,%6,%7}, {%8,%9}, {%0,%1,%2,%3};\n"
        : "+f"(c[0]), "+f"(c[1]), "+f"(c[2]), "+f"(c[3])
        : "r"(a0), "r"(a1), "r"(a2), "r"(a3), "r"(b0), "r"(b1));
}

__device__ __forceinline__ void ldsm4(uint32_t& r0, uint32_t& r1,
                                      uint32_t& r2, uint32_t& r3, uint32_t addr)
{
    asm volatile("ldmatrix.sync.aligned.m8n8.x4.shared.b16 {%0,%1,%2,%3}, [%4];"
                 : "=r"(r0), "=r"(r1), "=r"(r2), "=r"(r3) : "r"(addr));
}

__device__ __forceinline__ void ldsm4t(uint32_t& r0, uint32_t& r1,
                                       uint32_t& r2, uint32_t& r3, uint32_t addr)
{
    asm volatile("ldmatrix.sync.aligned.m8n8.x4.trans.shared.b16 {%0,%1,%2,%3}, [%4];"
                 : "=r"(r0), "=r"(r1), "=r"(r2), "=r"(r3) : "r"(addr));
}

__device__ __forceinline__ void cp16(uint32_t smem_addr, const void* gptr) {
    asm volatile("cp.async.ca.shared.global [%0], [%1], 16;\n"
                 :: "r"(smem_addr), "l"(gptr));
}
#define CP_COMMIT asm volatile("cp.async.commit_group;\n" ::)
#define CP_WAIT(n) asm volatile("cp.async.wait_group %0;\n" :: "n"(n))

__device__ __forceinline__ void store_out(float* p, float v) { *p = v; }
__device__ __forceinline__ void store_out(__half* p, float v) { *p = __float2half_rn(v); }

__device__ __forceinline__ uint32_t pack_h2(float a, float b) {
    __half2 h = __floats2half2_rn(a, b);
    return *(uint32_t*)&h;
}

// ---------------- weight transpose + fp16 convert -----------------------------
__global__ __launch_bounds__(256)
void transpose_half_kernel(const float* __restrict__ src, __half* __restrict__ dst,
                           int K, int N)
{
    __shared__ float t[32][33];
    const int kb = blockIdx.y * 32, nb = blockIdx.x * 32;
    const int tx = threadIdx.x & 31, ty = threadIdx.x >> 5;
    #pragma unroll
    for (int p = 0; p < 4; p++)
        t[ty + p * 8][tx] = src[(size_t)(kb + ty + p * 8) * N + nb + tx];
    __syncthreads();
    #pragma unroll
    for (int p = 0; p < 4; p++)
        dst[(size_t)(nb + ty + p * 8) * K + kb + tx] = __float2half_rn(t[tx][ty + p * 8]);
}

// ---------------- RMSNorm (fp16 output) ---------------------------------------
__global__ __launch_bounds__(256)
void rmsnorm_kernel(const float* __restrict__ x, const float* __restrict__ scale,
                    __half* __restrict__ out)
{
    int row = blockIdx.x;
    const float* xr = x + (size_t)row * Dm;
    float ss = 0.f;
    #pragma unroll
    for (int i = threadIdx.x; i < Dm; i += 256) { float v = xr[i]; ss += v * v; }
    __shared__ float red[256];
    red[threadIdx.x] = ss; __syncthreads();
    #pragma unroll
    for (int s = 128; s > 0; s >>= 1) {
        if (threadIdx.x < s) red[threadIdx.x] += red[threadIdx.x + s];
        __syncthreads();
    }
    float rms = rsqrtf(red[0] * (1.0f / Dm) + 1e-8f);
    __half* orow = out + (size_t)row * Dm;
    #pragma unroll
    for (int i = threadIdx.x; i < Dm; i += 256)
        orow[i] = __float2half_rn(scale[i] * xr[i] * rms);
}

// ---------------- FP16 GEMM (unchanged from R11) ------------------------------
#define TSH 72
#define TILE_H (128 * TSH)
#define GEMM_SMEM (4 * TILE_H * 2)

template<int EPI, typename TO>
__global__ __launch_bounds__(128, 2)
void gemm_tc(const __half* __restrict__ A, const __half* __restrict__ Bt,
             const float* __restrict__ bias, const float* __restrict__ resid,
             TO* __restrict__ C, int M, int N, int K)
{
    extern __shared__ __align__(16) char smemc[];
    const int tid = threadIdx.x, warp = tid >> 5, lane = tid & 31;
    const int bm = blockIdx.y * 128, bn = blockIdx.x * 128;
    const int warpM = (warp & 1) * 64, warpN = (warp >> 1) * 64;
    const int r0 = lane >> 2, c0 = lane & 3;
    float c[4][8][4] = {};

    const uint32_t sA = (uint32_t)__cvta_generic_to_shared(smemc);
    const uint32_t sB = sA + 2 * TILE_H * 2;

    const uint32_t aLane = sA +
        (uint32_t)((warpM + (lane & 15)) * TSH * 2 + ((lane >> 4) << 4));
    const uint32_t bLane = sB +
        (uint32_t)((warpN + (lane & 7) + ((lane >> 4) << 3)) * TSH * 2 +
                   (((lane >> 3) & 1) << 4));

    const int nk = K >> 6;

    auto load_tile = [&](int i, int buf) {
        const int k0 = i << 6;
        #pragma unroll
        for (int p = 0; p < 8; p++) {
            int idx = tid + p * 128;
            int m = idx >> 3, seg = idx & 7;
            uint32_t off = (uint32_t)(buf * TILE_H * 2 + m * TSH * 2 + seg * 16);
            cp16(sA + off, &A[(size_t)(bm + m) * K + k0 + seg * 8]);
            cp16(sB + off, &Bt[(size_t)(bn + m) * K + k0 + seg * 8]);
        }
    };

    load_tile(0, 0);
    CP_COMMIT;

    for (int i = 0; i < nk; i++) {
        const int buf = i & 1;
        CP_WAIT(0);
        __syncthreads();
        if (i + 1 < nk) {
            load_tile(i + 1, buf ^ 1);
            CP_COMMIT;
        }
        const uint32_t bufOff = (uint32_t)(buf * TILE_H * 2);
        #pragma unroll
        for (int kk = 0; kk < 64; kk += 16) {
            uint32_t a[4][4], b[8][2];
            #pragma unroll
            for (int mt = 0; mt < 4; mt++)
                ldsm4(a[mt][0], a[mt][1], a[mt][2], a[mt][3],
                      aLane + bufOff + (uint32_t)(mt * 16 * TSH * 2 + kk * 2));
            #pragma unroll
            for (int np = 0; np < 4; np++)
                ldsm4(b[2 * np][0], b[2 * np][1], b[2 * np + 1][0], b[2 * np + 1][1],
                      bLane + bufOff + (uint32_t)(np * 16 * TSH * 2 + kk * 2));
            #pragma unroll
            for (int mt = 0; mt < 4; mt++)
                #pragma unroll
                for (int nt = 0; nt < 8; nt++)
                    mma_f16(c[mt][nt], a[mt][0], a[mt][1], a[mt][2], a[mt][3],
                            b[nt][0], b[nt][1]);
        }
    }

    #pragma unroll
    for (int mt = 0; mt < 4; mt++) {
        #pragma unroll
        for (int nt = 0; nt < 8; nt++) {
            #pragma unroll
            for (int ci = 0; ci < 4; ci++) {
                int row = bm + warpM + mt * 16 + r0 + ((ci >= 2) ? 8 : 0);
                int col = bn + warpN + nt * 8 + c0 * 2 + (ci & 1);
                float v = c[mt][nt][ci] + bias[col];
                if (EPI == 1) v += resid[(size_t)row * N + col];
                if (EPI == 2) v = 0.5f * v * (1.0f + erff(v * 0.70710678118654752f));
                store_out(&C[(size_t)row * N + col], v);
            }
        }
    }
}

// ---------------- fused flash attention, fp16 mma ----------------------------
// Tiles (halves, stride 72 = 144B rows): Q[128], K[64], V[64], P[128]
#define FSH 72
#define FLASH_SMEM ((128 + 64 + 64 + 128) * FSH * 2)

__global__ __launch_bounds__(256, 2)
void flash_attn(const float* __restrict__ qkv, __half* __restrict__ attnout)
{
    extern __shared__ __align__(16) char smc[];
    const uint32_t smQ = (uint32_t)__cvta_generic_to_shared(smc);
    const uint32_t smK = smQ + 128 * FSH * 2;
    const uint32_t smV = smK + 64 * FSH * 2;
    const uint32_t smP = smV + 64 * FSH * 2;
    __half* Qh = (__half*)smc;
    __half* Kh = Qh + 128 * FSH;
    __half* Vh = Kh + 64 * FSH;
    __half* Ph = Vh + 64 * FSH;

    const int bh = blockIdx.y, b = bh >> 4, h = bh & 15;
    const int q0 = blockIdx.x * 128;
    const int tid = threadIdx.x, warp = tid >> 5, lane = tid & 31;
    const int r0 = lane >> 2, c0 = lane & 3;
    const int qrow = warp * 16;
    const float slope = exp2f(-0.5f * (float)(h + 1));
    const size_t base = (size_t)b * Sq * (3 * Dm) + (size_t)h * DH;

    // fragment base addresses
    const uint32_t aQ = smQ + (uint32_t)((qrow + (lane & 15)) * FSH * 2 + ((lane >> 4) << 4));
    const uint32_t bK = smK + (uint32_t)(((lane & 7) + ((lane >> 4) << 3)) * FSH * 2 +
                                         (((lane >> 3) & 1) << 4));
    const uint32_t aP = smP + (uint32_t)((qrow + (lane & 15)) * FSH * 2 + ((lane >> 4) << 4));
    // V trans: lanes -> rows (t) = (lane&7) + ((lane>>3)&1)*8, col halves = (lane>>4)*8
    const uint32_t bV = smV + (uint32_t)((((lane & 7) + (((lane >> 3) & 1) << 3)) * FSH +
                                          ((lane >> 4) << 3)) * 2);

    // Load Q tile: 128 x 64 -> fp16
    #pragma unroll
    for (int p = 0; p < 8; p++) {
        int idx = tid + p * 256;
        int r = idx >> 4, d4 = idx & 15;
        float4 v = *(const float4*)&qkv[base + (size_t)(q0 + r) * (3 * Dm) + d4 * 4];
        uint2 pk = make_uint2(pack_h2(v.x, v.y), pack_h2(v.z, v.w));
        *(uint2*)&Qh[r * FSH + d4 * 4] = pk;
    }

    float m_i[2] = {-1e30f, -1e30f};
    float l_i[2] = {0.f, 0.f};
    float o[8][4] = {};

    for (int t0 = 0; t0 < Sq; t0 += 64) {
        __syncthreads();
        #pragma unroll
        for (int p = 0; p < 4; p++) {
            int idx = tid + p * 256;
            int r = idx >> 4, d4 = idx & 15;
            const float* src = &qkv[base + (size_t)(t0 + r) * (3 * Dm) + d4 * 4];
            float4 vk = *(const float4*)(src + Dm);
            float4 vv = *(const float4*)(src + 2 * Dm);
            *(uint2*)&Kh[r * FSH + d4 * 4] =
                make_uint2(pack_h2(vk.x, vk.y), pack_h2(vk.z, vk.w));
            *(uint2*)&Vh[r * FSH + d4 * 4] =
                make_uint2(pack_h2(vv.x, vv.y), pack_h2(vv.z, vv.w));
        }
        __syncthreads();

        // S = Q @ K^T : warp 16 x 64, fp16 mma
        float s[8][4] = {};
        #pragma unroll
        for (int kk = 0; kk < 64; kk += 16) {
            uint32_t a0, a1, a2, a3, bfr[8][2];
            ldsm4(a0, a1, a2, a3, aQ + kk * 2);
            #pragma unroll
            for (int np = 0; np < 4; np++)
                ldsm4(bfr[2 * np][0], bfr[2 * np][1],
                      bfr[2 * np + 1][0], bfr[2 * np + 1][1],
                      bK + (uint32_t)(np * 16 * FSH * 2 + kk * 2));
            #pragma unroll
            for (int nt = 0; nt < 8; nt++)
                mma_f16(s[nt], a0, a1, a2, a3, bfr[nt][0], bfr[nt][1]);
        }

        const int si0 = q0 + qrow + r0, si1 = si0 + 8;
        float mx0 = -1e30f, mx1 = -1e30f;
        #pragma unroll
        for (int nt = 0; nt < 8; nt++) {
            int tj = t0 + nt * 8 + c0 * 2;
            s[nt][0] = s[nt][0] * 0.125f - slope * fabsf((float)(si0 - tj));
            s[nt][1] = s[nt][1] * 0.125f - slope * fabsf((float)(si0 - tj - 1));
            s[nt][2] = s[nt][2] * 0.125f - slope * fabsf((float)(si1 - tj));
            s[nt][3] = s[nt][3] * 0.125f - slope * fabsf((float)(si1 - tj - 1));
            mx0 = fmaxf(mx0, fmaxf(s[nt][0], s[nt][1]));
            mx1 = fmaxf(mx1, fmaxf(s[nt][2], s[nt][3]));
        }
        mx0 = fmaxf(mx0, __shfl_xor_sync(0xffffffffu, mx0, 1));
        mx0 = fmaxf(mx0, __shfl_xor_sync(0xffffffffu, mx0, 2));
        mx1 = fmaxf(mx1, __shfl_xor_sync(0xffffffffu, mx1, 1));
        mx1 = fmaxf(mx1, __shfl_xor_sync(0xffffffffu, mx1, 2));

        float mn0 = fmaxf(m_i[0], mx0), mn1 = fmaxf(m_i[1], mx1);
        float corr0 = __expf(m_i[0] - mn0), corr1 = __expf(m_i[1] - mn1);
        m_i[0] = mn0; m_i[1] = mn1;

        float sum0 = 0.f, sum1 = 0.f;
        #pragma unroll
        for (int nt = 0; nt < 8; nt++) {
            s[nt][0] = __expf(s[nt][0] - mn0);
            s[nt][1] = __expf(s[nt][1] - mn0);
            s[nt][2] = __expf(s[nt][2] - mn1);
            s[nt][3] = __expf(s[nt][3] - mn1);
            sum0 += s[nt][0] + s[nt][1];
            sum1 += s[nt][2] + s[nt][3];
            *(uint32_t*)&Ph[(qrow + r0) * FSH + nt * 8 + c0 * 2] =
                pack_h2(s[nt][0], s[nt][1]);
            *(uint32_t*)&Ph[(qrow + r0 + 8) * FSH + nt * 8 + c0 * 2] =
                pack_h2(s[nt][2], s[nt][3]);
        }
        sum0 += __shfl_xor_sync(0xffffffffu, sum0, 1);
        sum0 += __shfl_xor_sync(0xffffffffu, sum0, 2);
        sum1 += __shfl_xor_sync(0xffffffffu, sum1, 1);
        sum1 += __shfl_xor_sync(0xffffffffu, sum1, 2);
        l_i[0] = l_i[0] * corr0 + sum0;
        l_i[1] = l_i[1] * corr1 + sum1;
        #pragma unroll
        for (int nt = 0; nt < 8; nt++) {
            o[nt][0] *= corr0; o[nt][1] *= corr0;
            o[nt][2] *= corr1; o[nt][3] *= corr1;
        }
        __syncwarp();

        // O += P @ V : A from Ph (ldsm4), B from Vh via ldmatrix.trans
        #pragma unroll
        for (int kk = 0; kk < 64; kk += 16) {
            uint32_t a0, a1, a2, a3, bfr[8][2];
            ldsm4(a0, a1, a2, a3, aP + kk * 2);
            #pragma unroll
            for (int np = 0; np < 4; np++)
                ldsm4t(bfr[2 * np][0], bfr[2 * np][1],
                       bfr[2 * np + 1][0], bfr[2 * np + 1][1],
                       bV + (uint32_t)(kk * FSH * 2 + np * 32));
            #pragma unroll
            for (int nt = 0; nt < 8; nt++)
                mma_f16(o[nt], a0, a1, a2, a3, bfr[nt][0], bfr[nt][1]);
        }
    }

    float inv0 = 1.f / l_i[0], inv1 = 1.f / l_i[1];
    size_t obase = ((size_t)b * Sq + q0 + qrow) * Dm + (size_t)h * DH;
    #pragma unroll
    for (int nt = 0; nt < 8; nt++) {
        int d = nt * 8 + c0 * 2;
        attnout[obase + (size_t)r0 * Dm + d]           = __float2half_rn(o[nt][0] * inv0);
        attnout[obase + (size_t)r0 * Dm + d + 1]       = __float2half_rn(o[nt][1] * inv0);
        attnout[obase + (size_t)(r0 + 8) * Dm + d]     = __float2half_rn(o[nt][2] * inv1);
        attnout[obase + (size_t)(r0 + 8) * Dm + d + 1] = __float2half_rn(o[nt][3] * inv1);
    }
}

// ---------------- host driver ------------------------------------------------
extern "C" void kernel_launch(void* const* d_in, const int* in_sizes, int n_in,
                              void* d_out, int out_size)
{
    const float* x      = (const float*)d_in[0];
    const float* scale1 = (const float*)d_in[1];
    const float* scale2 = (const float*)d_in[2];
    const float* w_qkv  = (const float*)d_in[3];
    const float* b_qkv  = (const float*)d_in[4];
    const float* w_out  = (const float*)d_in[5];
    const float* b_out  = (const float*)d_in[6];
    const float* w1     = (const float*)d_in[7];
    const float* b1     = (const float*)d_in[8];
    const float* w2     = (const float*)d_in[9];
    const float* b2     = (const float*)d_in[10];
    float* out = (float*)d_out;

    void *p_xn, *p_qkv, *p_attnout, *p_x2, *p_h;
    void *p_wqkv, *p_wout, *p_w1, *p_w2;
    cudaGetSymbolAddress(&p_xn, g_xn);
    cudaGetSymbolAddress(&p_qkv, g_qkv);
    cudaGetSymbolAddress(&p_attnout, g_attnout);
    cudaGetSymbolAddress(&p_x2, g_x2);
    cudaGetSymbolAddress(&p_h, g_h);
    cudaGetSymbolAddress(&p_wqkv, g_wT_qkv);
    cudaGetSymbolAddress(&p_wout, g_wT_out);
    cudaGetSymbolAddress(&p_w1, g_wT1);
    cudaGetSymbolAddress(&p_w2, g_wT2);
    __half* xn      = (__half*)p_xn;
    float*  qkv     = (float*)p_qkv;
    __half* attnout = (__half*)p_attnout;
    float*  x2      = (float*)p_x2;
    __half* hbuf    = (__half*)p_h;
    __half* wTqkv   = (__half*)p_wqkv;
    __half* wTout   = (__half*)p_wout;
    __half* wT1     = (__half*)p_w1;
    __half* wT2     = (__half*)p_w2;

    cudaFuncSetAttribute(flash_attn, cudaFuncAttributeMaxDynamicSharedMemorySize,
                         FLASH_SMEM);
    cudaFuncSetAttribute(gemm_tc<0, float>, cudaFuncAttributeMaxDynamicSharedMemorySize,
                         GEMM_SMEM);
    cudaFuncSetAttribute(gemm_tc<1, float>, cudaFuncAttributeMaxDynamicSharedMemorySize,
                         GEMM_SMEM);
    cudaFuncSetAttribute(gemm_tc<2, __half>, cudaFuncAttributeMaxDynamicSharedMemorySize,
                         GEMM_SMEM);

    // 0) transpose + fp16 weights -> [N][K]
    transpose_half_kernel<<<dim3(3 * Dm / 32, Dm / 32), 256>>>(w_qkv, wTqkv, Dm, 3 * Dm);
    transpose_half_kernel<<<dim3(Dm / 32, Dm / 32), 256>>>(w_out, wTout, Dm, Dm);
    transpose_half_kernel<<<dim3(DFF / 32, Dm / 32), 256>>>(w1, wT1, Dm, DFF);
    transpose_half_kernel<<<dim3(Dm / 32, DFF / 32), 256>>>(w2, wT2, DFF, Dm);

    // 1) RMSNorm 1 -> fp16 xn
    rmsnorm_kernel<<<Mrows, 256>>>(x, scale1, xn);

    // 2) QKV projection (fp16 in, fp32 out)
    gemm_tc<0, float><<<dim3(3 * Dm / 128, Mrows / 128), 128, GEMM_SMEM>>>(
        xn, wTqkv, b_qkv, nullptr, qkv, Mrows, 3 * Dm, Dm);

    // 3-5) fused attention (fp16 mma) -> fp16 attnout
    flash_attn<<<dim3(Sq / 128, BH), 256, FLASH_SMEM>>>(qkv, attnout);

    // 6) out projection + residual (fp32 out)
    gemm_tc<1, float><<<dim3(Dm / 128, Mrows / 128), 128, GEMM_SMEM>>>(
        attnout, wTout, b_out, x, x2, Mrows, Dm, Dm);

    // 7) RMSNorm 2 -> fp16 xn
    rmsnorm_kernel<<<Mrows, 256>>>(x2, scale2, xn);

    // 8) FFN up + GELU -> fp16 hbuf
    gemm_tc<2, __half><<<dim3(DFF / 128, Mrows / 128), 128, GEMM_SMEM>>>(
        xn, wT1, b1, nullptr, hbuf, Mrows, DFF, Dm);

    // 9) FFN down + residual (fp32 out)
    gemm_tc<1, float><<<dim3(Dm / 128, Mrows / 128), 128, GEMM_SMEM>>>(
        hbuf, wT2, b2, x2, out, Mrows, Dm, DFF);
}